// round 11
// baseline (speedup 1.0000x reference)
#include <cuda_runtime.h>
#include <cstdint>

#define N_NODES 50000
#define N_EDGES 800000
#define IN_C  64
#define HID_C 128
#define OUT_C 40
#define CAP   96
#define NB    391   // ceil(50000/128)

// ---------------- scratch ----------------
__device__ float g_u1[N_NODES * IN_C];
__device__ float g_h1[N_NODES * HID_C];     // k1a out; reused as k2a out (t)
__device__ float g_hrel[N_NODES * HID_C];
__device__ float g_u2[N_NODES * HID_C];
__device__ int   g_deg[N_NODES];
__device__ int   g_bucket[N_NODES * CAP];
__device__ int   g_ei_is64;

// ---------------- helpers ----------------
__device__ __forceinline__ uint32_t cvt_tf32(float v) {
    uint32_t r;
    asm("cvt.rna.tf32.f32 %0, %1;" : "=r"(r) : "f"(v));
    return r;
}
__device__ __forceinline__ void mma_tf32(float* d, const uint32_t* a,
                                         uint32_t b0, uint32_t b1) {
    asm volatile(
        "mma.sync.aligned.m16n8k8.row.col.f32.tf32.tf32.f32 "
        "{%0,%1,%2,%3}, {%4,%5,%6,%7}, {%8,%9}, {%0,%1,%2,%3};"
        : "+f"(d[0]), "+f"(d[1]), "+f"(d[2]), "+f"(d[3])
        : "r"(a[0]), "r"(a[1]), "r"(a[2]), "r"(a[3]), "r"(b0), "r"(b1));
}

// ---------------- dtype detection ----------------
__global__ void detect_ei_kernel(const unsigned int* __restrict__ w) {
    int ok = (w[2 * threadIdx.x + 1] == 0u) ? 1 : 0;
    int all = __syncthreads_and(ok);
    if (threadIdx.x == 0) g_ei_is64 = all;
}

// ---------------- bucket fill ----------------
__global__ void __launch_bounds__(256) fill_kernel(const void* __restrict__ eiv) {
    int e = blockIdx.x * 256 + threadIdx.x;
    int s, d;
    if (g_ei_is64) {
        const long long* ei = (const long long*)eiv;
        s = (int)ei[e]; d = (int)ei[N_EDGES + e];
    } else {
        const int* ei = (const int*)eiv;
        s = ei[e]; d = ei[N_EDGES + e];
    }
    if ((unsigned)s >= N_NODES || (unsigned)d >= N_NODES) return;
    int pos = atomicAdd(&g_deg[d], 1);
    if (pos < CAP) g_bucket[d * CAP + pos] = s;
}

// ---------------- gather-aggregate layer 1 ----------------
__global__ void __launch_bounds__(256) agg1_kernel(
    const float* __restrict__ x, const float* __restrict__ eps1p,
    float* __restrict__ u1)
{
    int n = blockIdx.x * 8 + (threadIdx.x >> 5);
    int lane = threadIdx.x & 31;
    int deg = g_deg[n]; if (deg > CAP) deg = CAP;
    const int* bkt = &g_bucket[n * CAP];
    float2 acc = make_float2(0.f, 0.f);
    for (int i = 0; i < deg; i++) {
        int s = bkt[i];
        float2 v = *reinterpret_cast<const float2*>(x + (size_t)s * IN_C + lane * 2);
        acc.x += v.x; acc.y += v.y;
    }
    float ep = 1.0f + *eps1p;
    float2 xv = *reinterpret_cast<const float2*>(x + (size_t)n * IN_C + lane * 2);
    *reinterpret_cast<float2*>(u1 + (size_t)n * IN_C + lane * 2) =
        make_float2(ep * xv.x + acc.x, ep * xv.y + acc.y);
}

// ---------------- gather-aggregate layer 2 ----------------
__global__ void __launch_bounds__(256) agg2_kernel(
    const float* __restrict__ h, const float* __restrict__ eps2p,
    float* __restrict__ u2)
{
    int n = blockIdx.x * 8 + (threadIdx.x >> 5);
    int lane = threadIdx.x & 31;
    int deg = g_deg[n]; if (deg > CAP) deg = CAP;
    const int* bkt = &g_bucket[n * CAP];
    float4 acc = make_float4(0.f, 0.f, 0.f, 0.f);
    for (int i = 0; i < deg; i++) {
        int s = bkt[i];
        float4 v = *reinterpret_cast<const float4*>(h + (size_t)s * HID_C + lane * 4);
        acc.x += v.x; acc.y += v.y; acc.z += v.z; acc.w += v.w;
    }
    float ep = 1.0f + *eps2p;
    float4 hv = *reinterpret_cast<const float4*>(h + (size_t)n * HID_C + lane * 4);
    *reinterpret_cast<float4*>(u2 + (size_t)n * HID_C + lane * 4) =
        make_float4(ep * hv.x + acc.x, ep * hv.y + acc.y,
                    ep * hv.z + acc.z, ep * hv.w + acc.w);
}

// ================= TF32 mma GEMM: [128 nodes] x [K -> 128], relu ==========
// 256 threads = 8 warps; warp w computes m16 stripe rows [w*16, w*16+16),
// all 128 output cols (16 n8-tiles). 3xTF32 split for fp32-class accuracy.
// smem: xin f32 [128][K+4] | whi [K][136] | wlo [K][136] | bias [128]
#define WPAD 136
template<int K>
__device__ __forceinline__ void gemm_tf32_body(
    const float* __restrict__ in,    // [N][K] node-major
    const float* __restrict__ w,     // [K][128] row-major
    const float* __restrict__ b,     // [128]
    float* __restrict__ outp)        // [N][128] node-major, relu
{
    constexpr int APAD = K + 4;
    extern __shared__ float sm[];
    float* xin  = sm;                         // [128][APAD]
    float* whi  = xin + 128 * APAD;           // [K][WPAD]
    float* wlo  = whi + K * WPAD;             // [K][WPAD]
    float* bias = wlo + K * WPAD;             // [128]

    const int tid = threadIdx.x;
    const int n0 = blockIdx.x * 128;

    // stage weights as tf32 hi/lo
    for (int i = tid; i < K * 128; i += 256) {
        int k = i >> 7, n = i & 127;
        float v = w[i];
        uint32_t h = cvt_tf32(v);
        float hf = __uint_as_float(h);
        uint32_t l = cvt_tf32(v - hf);
        whi[k * WPAD + n] = hf;
        wlo[k * WPAD + n] = __uint_as_float(l);
    }
    if (tid < 128) bias[tid] = b[tid];

    // stage activations (zero-pad tail rows)
    for (int i = tid; i < 128 * K; i += 256) {
        int n = i / K, c = i - n * K;
        int g = n0 + n;
        xin[n * APAD + c] = (g < N_NODES) ? in[(size_t)g * K + c] : 0.0f;
    }
    __syncthreads();

    const int lane = tid & 31;
    const int m0 = (tid >> 5) * 16;
    const int r = lane >> 2;          // 0..7
    const int c = lane & 3;           // 0..3

    float acc[16][4];
    #pragma unroll
    for (int nt = 0; nt < 16; nt++)
        #pragma unroll
        for (int i = 0; i < 4; i++) acc[nt][i] = 0.0f;

    for (int k0 = 0; k0 < K; k0 += 8) {
        // A fragments (m16 x k8), converted to tf32 hi/lo on the fly
        float af0 = xin[(m0 + r) * APAD + k0 + c];
        float af1 = xin[(m0 + r + 8) * APAD + k0 + c];
        float af2 = xin[(m0 + r) * APAD + k0 + c + 4];
        float af3 = xin[(m0 + r + 8) * APAD + k0 + c + 4];
        uint32_t ah[4], al[4];
        ah[0] = cvt_tf32(af0); al[0] = cvt_tf32(af0 - __uint_as_float(ah[0]));
        ah[1] = cvt_tf32(af1); al[1] = cvt_tf32(af1 - __uint_as_float(ah[1]));
        ah[2] = cvt_tf32(af2); al[2] = cvt_tf32(af2 - __uint_as_float(ah[2]));
        ah[3] = cvt_tf32(af3); al[3] = cvt_tf32(af3 - __uint_as_float(ah[3]));

        const int krow0 = (k0 + c) * WPAD;
        const int krow1 = (k0 + c + 4) * WPAD;
        #pragma unroll
        for (int nt = 0; nt < 16; nt++) {
            int col = nt * 8 + r;
            uint32_t bh0 = __float_as_uint(whi[krow0 + col]);
            uint32_t bh1 = __float_as_uint(whi[krow1 + col]);
            uint32_t bl0 = __float_as_uint(wlo[krow0 + col]);
            uint32_t bl1 = __float_as_uint(wlo[krow1 + col]);
            mma_tf32(acc[nt], ah, bh0, bh1);
            mma_tf32(acc[nt], al, bh0, bh1);
            mma_tf32(acc[nt], ah, bl0, bl1);
        }
    }

    // epilogue: bias + relu, store node-major
    const int g0 = n0 + m0 + r;
    const int g1 = g0 + 8;
    #pragma unroll
    for (int nt = 0; nt < 16; nt++) {
        int col = nt * 8 + 2 * c;
        float b0v = bias[col], b1v = bias[col + 1];
        if (g0 < N_NODES) {
            float2 v = make_float2(fmaxf(acc[nt][0] + b0v, 0.0f),
                                   fmaxf(acc[nt][1] + b1v, 0.0f));
            *reinterpret_cast<float2*>(outp + (size_t)g0 * HID_C + col) = v;
        }
        if (g1 < N_NODES) {
            float2 v = make_float2(fmaxf(acc[nt][2] + b0v, 0.0f),
                                   fmaxf(acc[nt][3] + b1v, 0.0f));
            *reinterpret_cast<float2*>(outp + (size_t)g1 * HID_C + col) = v;
        }
    }
}

#define SMEM_G64  ((128 * 68  + 2 * 64  * WPAD + 128) * 4)
#define SMEM_G128 ((128 * 132 + 2 * 128 * WPAD + 128) * 4)

__global__ void __launch_bounds__(256, 1) k1a_kernel(
    const float* __restrict__ in, const float* __restrict__ w,
    const float* __restrict__ b, float* __restrict__ outp)
{ gemm_tf32_body<64>(in, w, b, outp); }

__global__ void __launch_bounds__(256, 1) k1b_kernel(
    const float* __restrict__ in, const float* __restrict__ w,
    const float* __restrict__ b, float* __restrict__ outp)
{ gemm_tf32_body<128>(in, w, b, outp); }

__global__ void __launch_bounds__(256, 1) k2a_kernel(
    const float* __restrict__ in, const float* __restrict__ w,
    const float* __restrict__ b, float* __restrict__ outp)
{ gemm_tf32_body<128>(in, w, b, outp); }

// ---------------- k2b: t(128) -> 40 logits + log_softmax ----------------
#define C_W2BT 0                          // [40][132]
#define C_TS   (40 * 132)                 // [128][132]
#define C_OO   (C_TS + 128 * 132)         // [128][40]
#define C_B2B  (C_OO + 128 * 40)          // [64]
#define C_CORR (C_B2B + 64)               // [128]
#define SMEM_K2B ((C_CORR + 128) * 4)

__global__ void __launch_bounds__(256) k2b_kernel(
    const float* __restrict__ t, const float* __restrict__ w2b,
    const float* __restrict__ b2b, float* __restrict__ out)
{
    extern __shared__ float sm[];
    float* w2bT = sm + C_W2BT;
    float* tS   = sm + C_TS;
    float* oout = sm + C_OO;
    float* b2bs = sm + C_B2B;
    float* corr = sm + C_CORR;

    const int tid = threadIdx.x;
    const int n0 = blockIdx.x * 128;

    for (int i = tid; i < HID_C * OUT_C; i += 256) {
        int c = i / OUT_C, j = i - c * OUT_C;
        w2bT[j * 132 + c] = w2b[i];
    }
    if (tid < OUT_C) b2bs[tid] = b2b[tid];
    for (int i = tid; i < 128 * HID_C; i += 256) {
        int n = i >> 7, c = i & 127;
        int g = n0 + n;
        tS[n * 132 + c] = (g < N_NODES) ? t[(size_t)g * HID_C + c] : 0.0f;
    }
    __syncthreads();

    for (int idx = tid; idx < 128 * OUT_C; idx += 256) {
        int n = idx / OUT_C;
        int j = idx - n * OUT_C;
        float a = b2bs[j];
        const float* wr = &w2bT[j * 132];
        const float* tr = &tS[n * 132];
        #pragma unroll
        for (int c = 0; c < HID_C; c += 4) {
            float4 wv = *reinterpret_cast<const float4*>(wr + c);
            float4 tv = *reinterpret_cast<const float4*>(tr + c);
            a += wv.x * tv.x + wv.y * tv.y + wv.z * tv.z + wv.w * tv.w;
        }
        oout[idx] = a;
    }
    __syncthreads();

    if (tid < 128) {
        const float* o = &oout[tid * OUT_C];
        float m = o[0];
        #pragma unroll
        for (int j = 1; j < OUT_C; j++) m = fmaxf(m, o[j]);
        float s = 0.0f;
        #pragma unroll
        for (int j = 0; j < OUT_C; j++) s += __expf(o[j] - m);
        corr[tid] = m + logf(s);
    }
    __syncthreads();

    for (int idx = tid; idx < 128 * OUT_C; idx += 256) {
        int n = idx / OUT_C;
        int g = n0 + n;
        if (g < N_NODES) out[(size_t)g * OUT_C + (idx - n * OUT_C)] = oout[idx] - corr[n];
    }
}

// ================= launch =================
extern "C" void kernel_launch(void* const* d_in, const int* in_sizes, int n_in,
                              void* d_out, int out_size)
{
    const float* x    = (const float*)d_in[0];
    const void*  ei   = d_in[1];
    const float* w1a  = (const float*)d_in[2];
    const float* b1a  = (const float*)d_in[3];
    const float* w1b  = (const float*)d_in[4];
    const float* b1b  = (const float*)d_in[5];
    const float* eps1 = (const float*)d_in[6];
    const float* w2a  = (const float*)d_in[7];
    const float* b2a  = (const float*)d_in[8];
    const float* w2b  = (const float*)d_in[9];
    const float* b2b  = (const float*)d_in[10];
    const float* eps2 = (const float*)d_in[11];
    float* out = (float*)d_out;

    float *u1, *h1, *hrel, *u2;
    int *deg;
    cudaGetSymbolAddress((void**)&u1, g_u1);
    cudaGetSymbolAddress((void**)&h1, g_h1);
    cudaGetSymbolAddress((void**)&hrel, g_hrel);
    cudaGetSymbolAddress((void**)&u2, g_u2);
    cudaGetSymbolAddress((void**)&deg, g_deg);

    cudaFuncSetAttribute(k1a_kernel, cudaFuncAttributeMaxDynamicSharedMemorySize, SMEM_G64);
    cudaFuncSetAttribute(k1b_kernel, cudaFuncAttributeMaxDynamicSharedMemorySize, SMEM_G128);
    cudaFuncSetAttribute(k2a_kernel, cudaFuncAttributeMaxDynamicSharedMemorySize, SMEM_G128);
    cudaFuncSetAttribute(k2b_kernel, cudaFuncAttributeMaxDynamicSharedMemorySize, SMEM_K2B);

    detect_ei_kernel<<<1, 512>>>((const unsigned int*)ei);
    cudaMemsetAsync(deg, 0, N_NODES * sizeof(int));
    fill_kernel<<<N_EDGES / 256, 256>>>(ei);

    // layer 1
    agg1_kernel<<<N_NODES / 8, 256>>>(x, eps1, u1);
    k1a_kernel<<<NB, 256, SMEM_G64>>>(u1, w1a, b1a, h1);
    k1b_kernel<<<NB, 256, SMEM_G128>>>(h1, w1b, b1b, hrel);

    // layer 2
    agg2_kernel<<<N_NODES / 8, 256>>>(hrel, eps2, u2);
    k2a_kernel<<<NB, 256, SMEM_G128>>>(u2, w2a, b2a, h1);   // reuse h1 as t
    k2b_kernel<<<NB, 256, SMEM_K2B>>>(h1, w2b, b2b, out);
}

// round 12
// speedup vs baseline: 1.1172x; 1.1172x over previous
#include <cuda_runtime.h>
#include <cuda_bf16.h>
#include <cstdint>

#define N_NODES 50000
#define N_EDGES 800000
#define IN_C  64
#define HID_C 128
#define OUT_C 40
#define CAP   96
#define NB    391   // ceil(50000/128)

// ---------------- scratch ----------------
__device__ float g_u1[N_NODES * IN_C];
__device__ float g_h1[N_NODES * HID_C];     // k1a out; reused as k2a out (t)
__device__ float g_hrel[N_NODES * HID_C];
__device__ float g_u2[N_NODES * HID_C];
__device__ int   g_deg[N_NODES];
__device__ int   g_bucket[N_NODES * CAP];
__device__ int   g_ei_is64;

// ---------------- helpers ----------------
// split f32 -> (bf16 hi, bf16 residual); explicit scalar packing, lo half = even k
__device__ __forceinline__ void split_pack(float va, float vb, uint32_t& p0, uint32_t& p1) {
    __nv_bfloat16 a0 = __float2bfloat16(va);
    __nv_bfloat16 b0 = __float2bfloat16(vb);
    float ra = va - __bfloat162float(a0);
    float rb = vb - __bfloat162float(b0);
    __nv_bfloat16 a1 = __float2bfloat16(ra);
    __nv_bfloat16 b1 = __float2bfloat16(rb);
    uint16_t ua0 = *reinterpret_cast<uint16_t*>(&a0);
    uint16_t ub0 = *reinterpret_cast<uint16_t*>(&b0);
    uint16_t ua1 = *reinterpret_cast<uint16_t*>(&a1);
    uint16_t ub1 = *reinterpret_cast<uint16_t*>(&b1);
    p0 = (uint32_t)ua0 | ((uint32_t)ub0 << 16);   // lo = k even, hi = k odd
    p1 = (uint32_t)ua1 | ((uint32_t)ub1 << 16);
}

__device__ __forceinline__ void mma_bf16(float* d, const uint32_t* a,
                                         uint32_t b0, uint32_t b1) {
    asm volatile(
        "mma.sync.aligned.m16n8k16.row.col.f32.bf16.bf16.f32 "
        "{%0,%1,%2,%3}, {%4,%5,%6,%7}, {%8,%9}, {%0,%1,%2,%3};"
        : "+f"(d[0]), "+f"(d[1]), "+f"(d[2]), "+f"(d[3])
        : "r"(a[0]), "r"(a[1]), "r"(a[2]), "r"(a[3]), "r"(b0), "r"(b1));
}

// ---------------- dtype detection ----------------
__global__ void detect_ei_kernel(const unsigned int* __restrict__ w) {
    int ok = (w[2 * threadIdx.x + 1] == 0u) ? 1 : 0;
    int all = __syncthreads_and(ok);
    if (threadIdx.x == 0) g_ei_is64 = all;
}

// ---------------- bucket fill ----------------
__global__ void __launch_bounds__(256) fill_kernel(const void* __restrict__ eiv) {
    int e = blockIdx.x * 256 + threadIdx.x;
    int s, d;
    if (g_ei_is64) {
        const long long* ei = (const long long*)eiv;
        s = (int)ei[e]; d = (int)ei[N_EDGES + e];
    } else {
        const int* ei = (const int*)eiv;
        s = ei[e]; d = ei[N_EDGES + e];
    }
    if ((unsigned)s >= N_NODES || (unsigned)d >= N_NODES) return;
    int pos = atomicAdd(&g_deg[d], 1);
    if (pos < CAP) g_bucket[d * CAP + pos] = s;
}

// ---------------- gather-aggregate layer 1 ----------------
__global__ void __launch_bounds__(256) agg1_kernel(
    const float* __restrict__ x, const float* __restrict__ eps1p,
    float* __restrict__ u1)
{
    int n = blockIdx.x * 8 + (threadIdx.x >> 5);
    int lane = threadIdx.x & 31;
    int deg = g_deg[n]; if (deg > CAP) deg = CAP;
    const int* bkt = &g_bucket[n * CAP];
    float2 acc = make_float2(0.f, 0.f);
    for (int i = 0; i < deg; i++) {
        int s = bkt[i];
        float2 v = *reinterpret_cast<const float2*>(x + (size_t)s * IN_C + lane * 2);
        acc.x += v.x; acc.y += v.y;
    }
    float ep = 1.0f + *eps1p;
    float2 xv = *reinterpret_cast<const float2*>(x + (size_t)n * IN_C + lane * 2);
    *reinterpret_cast<float2*>(u1 + (size_t)n * IN_C + lane * 2) =
        make_float2(ep * xv.x + acc.x, ep * xv.y + acc.y);
}

// ---------------- gather-aggregate layer 2 ----------------
__global__ void __launch_bounds__(256) agg2_kernel(
    const float* __restrict__ h, const float* __restrict__ eps2p,
    float* __restrict__ u2)
{
    int n = blockIdx.x * 8 + (threadIdx.x >> 5);
    int lane = threadIdx.x & 31;
    int deg = g_deg[n]; if (deg > CAP) deg = CAP;
    const int* bkt = &g_bucket[n * CAP];
    float4 acc = make_float4(0.f, 0.f, 0.f, 0.f);
    for (int i = 0; i < deg; i++) {
        int s = bkt[i];
        float4 v = *reinterpret_cast<const float4*>(h + (size_t)s * HID_C + lane * 4);
        acc.x += v.x; acc.y += v.y; acc.z += v.z; acc.w += v.w;
    }
    float ep = 1.0f + *eps2p;
    float4 hv = *reinterpret_cast<const float4*>(h + (size_t)n * HID_C + lane * 4);
    *reinterpret_cast<float4*>(u2 + (size_t)n * HID_C + lane * 4) =
        make_float4(ep * hv.x + acc.x, ep * hv.y + acc.y,
                    ep * hv.z + acc.z, ep * hv.w + acc.w);
}

// ========== bf16 3-split mma GEMM: [128 nodes] x [K -> 128], relu =========
// 512 threads = 16 warps: warp = (m-stripe wid&7, n-half wid>>3).
// smem u32 arrays: x0,x1 [128][KP+4] bf16x2 pairs; w0,w1 [KP][136]; bias f32.
#define WS 136
template<int K>
__device__ __forceinline__ void gemm_bf16_body(
    const float* __restrict__ in,    // [N][K] node-major
    const float* __restrict__ w,     // [K][128] row-major
    const float* __restrict__ b,     // [128]
    float* __restrict__ outp)        // [N][128] node-major, relu
{
    constexpr int KP = K / 2;        // packed k-pairs
    constexpr int XS = KP + 4;       // x row stride (u32)
    extern __shared__ uint32_t smu[];
    uint32_t* x0 = smu;                       // [128][XS]
    uint32_t* x1 = x0 + 128 * XS;
    uint32_t* w0 = x1 + 128 * XS;             // [KP][WS]
    uint32_t* w1 = w0 + KP * WS;
    float*  bias = (float*)(w1 + KP * WS);    // [128]

    const int tid = threadIdx.x;
    const int n0 = blockIdx.x * 128;

    // stage weights split+packed
    for (int i = tid; i < KP * 128; i += 512) {
        int kp = i >> 7, n = i & 127;
        float va = w[(2 * kp) * 128 + n];
        float vb = w[(2 * kp + 1) * 128 + n];
        uint32_t p0, p1;
        split_pack(va, vb, p0, p1);
        w0[kp * WS + n] = p0;
        w1[kp * WS + n] = p1;
    }
    if (tid < 128) bias[tid] = b[tid];

    // stage activations split+packed (zero-pad tail rows)
    for (int i = tid; i < 128 * KP; i += 512) {
        int n = i / KP, kp = i - n * KP;
        int g = n0 + n;
        float va = 0.0f, vb = 0.0f;
        if (g < N_NODES) {
            va = in[(size_t)g * K + 2 * kp];
            vb = in[(size_t)g * K + 2 * kp + 1];
        }
        uint32_t p0, p1;
        split_pack(va, vb, p0, p1);
        x0[n * XS + kp] = p0;
        x1[n * XS + kp] = p1;
    }
    __syncthreads();

    const int lane = tid & 31;
    const int wid = tid >> 5;
    const int m0 = (wid & 7) * 16;
    const int ntb = (wid >> 3) * 8;   // first n8-tile of this warp's half
    const int r = lane >> 2;          // 0..7
    const int c = lane & 3;           // 0..3

    float acc[8][4];
    #pragma unroll
    for (int j = 0; j < 8; j++)
        #pragma unroll
        for (int i = 0; i < 4; i++) acc[j][i] = 0.0f;

    #pragma unroll
    for (int kp0 = 0; kp0 < KP; kp0 += 8) {   // one k16 step per iter
        uint32_t ah[4], al[4];
        ah[0] = x0[(m0 + r) * XS + kp0 + c];
        ah[1] = x0[(m0 + r + 8) * XS + kp0 + c];
        ah[2] = x0[(m0 + r) * XS + kp0 + c + 4];
        ah[3] = x0[(m0 + r + 8) * XS + kp0 + c + 4];
        al[0] = x1[(m0 + r) * XS + kp0 + c];
        al[1] = x1[(m0 + r + 8) * XS + kp0 + c];
        al[2] = x1[(m0 + r) * XS + kp0 + c + 4];
        al[3] = x1[(m0 + r + 8) * XS + kp0 + c + 4];

        const int kr0 = (kp0 + c) * WS;
        const int kr1 = (kp0 + c + 4) * WS;
        #pragma unroll
        for (int j = 0; j < 8; j++) {
            int col = (ntb + j) * 8 + r;
            uint32_t bh0 = w0[kr0 + col];
            uint32_t bh1 = w0[kr1 + col];
            uint32_t bl0 = w1[kr0 + col];
            uint32_t bl1 = w1[kr1 + col];
            mma_bf16(acc[j], ah, bh0, bh1);   // x0*w0
            mma_bf16(acc[j], al, bh0, bh1);   // x1*w0
            mma_bf16(acc[j], ah, bl0, bl1);   // x0*w1
        }
    }

    // epilogue: bias + relu, node-major store
    const int g0 = n0 + m0 + r;
    const int g1 = g0 + 8;
    #pragma unroll
    for (int j = 0; j < 8; j++) {
        int col = (ntb + j) * 8 + 2 * c;
        float b0v = bias[col], b1v = bias[col + 1];
        if (g0 < N_NODES) {
            float2 v = make_float2(fmaxf(acc[j][0] + b0v, 0.0f),
                                   fmaxf(acc[j][1] + b1v, 0.0f));
            *reinterpret_cast<float2*>(outp + (size_t)g0 * HID_C + col) = v;
        }
        if (g1 < N_NODES) {
            float2 v = make_float2(fmaxf(acc[j][2] + b0v, 0.0f),
                                   fmaxf(acc[j][3] + b1v, 0.0f));
            *reinterpret_cast<float2*>(outp + (size_t)g1 * HID_C + col) = v;
        }
    }
}

#define SMEM_G64  ((2 * 128 * (32 + 4) + 2 * 32 * WS) * 4 + 512)
#define SMEM_G128 ((2 * 128 * (64 + 4) + 2 * 64 * WS) * 4 + 512)

__global__ void __launch_bounds__(512, 1) k1a_kernel(
    const float* __restrict__ in, const float* __restrict__ w,
    const float* __restrict__ b, float* __restrict__ outp)
{ gemm_bf16_body<64>(in, w, b, outp); }

__global__ void __launch_bounds__(512, 1) k1b_kernel(
    const float* __restrict__ in, const float* __restrict__ w,
    const float* __restrict__ b, float* __restrict__ outp)
{ gemm_bf16_body<128>(in, w, b, outp); }

__global__ void __launch_bounds__(512, 1) k2a_kernel(
    const float* __restrict__ in, const float* __restrict__ w,
    const float* __restrict__ b, float* __restrict__ outp)
{ gemm_bf16_body<128>(in, w, b, outp); }

// ---------------- k2b: t(128) -> 40 logits + log_softmax ----------------
#define C_W2BT 0                          // [40][132]
#define C_TS   (40 * 132)                 // [128][132]
#define C_OO   (C_TS + 128 * 132)         // [128][40]
#define C_B2B  (C_OO + 128 * 40)          // [64]
#define C_CORR (C_B2B + 64)               // [128]
#define SMEM_K2B ((C_CORR + 128) * 4)

__global__ void __launch_bounds__(256) k2b_kernel(
    const float* __restrict__ t, const float* __restrict__ w2b,
    const float* __restrict__ b2b, float* __restrict__ out)
{
    extern __shared__ float sm[];
    float* w2bT = sm + C_W2BT;
    float* tS   = sm + C_TS;
    float* oout = sm + C_OO;
    float* b2bs = sm + C_B2B;
    float* corr = sm + C_CORR;

    const int tid = threadIdx.x;
    const int n0 = blockIdx.x * 128;

    for (int i = tid; i < HID_C * OUT_C; i += 256) {
        int c = i / OUT_C, j = i - c * OUT_C;
        w2bT[j * 132 + c] = w2b[i];
    }
    if (tid < OUT_C) b2bs[tid] = b2b[tid];
    for (int i = tid; i < 128 * HID_C; i += 256) {
        int n = i >> 7, c = i & 127;
        int g = n0 + n;
        tS[n * 132 + c] = (g < N_NODES) ? t[(size_t)g * HID_C + c] : 0.0f;
    }
    __syncthreads();

    for (int idx = tid; idx < 128 * OUT_C; idx += 256) {
        int n = idx / OUT_C;
        int j = idx - n * OUT_C;
        float a = b2bs[j];
        const float* wr = &w2bT[j * 132];
        const float* tr = &tS[n * 132];
        #pragma unroll
        for (int c = 0; c < HID_C; c += 4) {
            float4 wv = *reinterpret_cast<const float4*>(wr + c);
            float4 tv = *reinterpret_cast<const float4*>(tr + c);
            a += wv.x * tv.x + wv.y * tv.y + wv.z * tv.z + wv.w * tv.w;
        }
        oout[idx] = a;
    }
    __syncthreads();

    if (tid < 128) {
        const float* o = &oout[tid * OUT_C];
        float m = o[0];
        #pragma unroll
        for (int j = 1; j < OUT_C; j++) m = fmaxf(m, o[j]);
        float s = 0.0f;
        #pragma unroll
        for (int j = 0; j < OUT_C; j++) s += __expf(o[j] - m);
        corr[tid] = m + logf(s);
    }
    __syncthreads();

    for (int idx = tid; idx < 128 * OUT_C; idx += 256) {
        int n = idx / OUT_C;
        int g = n0 + n;
        if (g < N_NODES) out[(size_t)g * OUT_C + (idx - n * OUT_C)] = oout[idx] - corr[n];
    }
}

// ================= launch =================
extern "C" void kernel_launch(void* const* d_in, const int* in_sizes, int n_in,
                              void* d_out, int out_size)
{
    const float* x    = (const float*)d_in[0];
    const void*  ei   = d_in[1];
    const float* w1a  = (const float*)d_in[2];
    const float* b1a  = (const float*)d_in[3];
    const float* w1b  = (const float*)d_in[4];
    const float* b1b  = (const float*)d_in[5];
    const float* eps1 = (const float*)d_in[6];
    const float* w2a  = (const float*)d_in[7];
    const float* b2a  = (const float*)d_in[8];
    const float* w2b  = (const float*)d_in[9];
    const float* b2b  = (const float*)d_in[10];
    const float* eps2 = (const float*)d_in[11];
    float* out = (float*)d_out;

    float *u1, *h1, *hrel, *u2;
    int *deg;
    cudaGetSymbolAddress((void**)&u1, g_u1);
    cudaGetSymbolAddress((void**)&h1, g_h1);
    cudaGetSymbolAddress((void**)&hrel, g_hrel);
    cudaGetSymbolAddress((void**)&u2, g_u2);
    cudaGetSymbolAddress((void**)&deg, g_deg);

    cudaFuncSetAttribute(k1a_kernel, cudaFuncAttributeMaxDynamicSharedMemorySize, SMEM_G64);
    cudaFuncSetAttribute(k1b_kernel, cudaFuncAttributeMaxDynamicSharedMemorySize, SMEM_G128);
    cudaFuncSetAttribute(k2a_kernel, cudaFuncAttributeMaxDynamicSharedMemorySize, SMEM_G128);
    cudaFuncSetAttribute(k2b_kernel, cudaFuncAttributeMaxDynamicSharedMemorySize, SMEM_K2B);

    detect_ei_kernel<<<1, 512>>>((const unsigned int*)ei);
    cudaMemsetAsync(deg, 0, N_NODES * sizeof(int));
    fill_kernel<<<N_EDGES / 256, 256>>>(ei);

    // layer 1
    agg1_kernel<<<N_NODES / 8, 256>>>(x, eps1, u1);
    k1a_kernel<<<NB, 512, SMEM_G64>>>(u1, w1a, b1a, h1);
    k1b_kernel<<<NB, 512, SMEM_G128>>>(h1, w1b, b1b, hrel);

    // layer 2
    agg2_kernel<<<N_NODES / 8, 256>>>(hrel, eps2, u2);
    k2a_kernel<<<NB, 512, SMEM_G128>>>(u2, w2a, b2a, h1);   // reuse h1 as t
    k2b_kernel<<<NB, 256, SMEM_K2B>>>(h1, w2b, b2b, out);
}

// round 13
// speedup vs baseline: 1.2408x; 1.1106x over previous
#include <cuda_runtime.h>
#include <cuda_bf16.h>
#include <cstdint>

#define N_NODES 50000
#define N_EDGES 800000
#define IN_C  64
#define HID_C 128
#define OUT_C 40
#define CAP   96
#define NB    391   // ceil(50000/128)

// ---------------- scratch ----------------
__device__ float g_u1[N_NODES * IN_C];
__device__ float g_hrel[N_NODES * HID_C];
__device__ float g_u2[N_NODES * HID_C];
__device__ int   g_deg[N_NODES];
__device__ int   g_bucket[N_NODES * CAP];
__device__ int   g_ei_is64;

// ---------------- helpers ----------------
// split f32 -> (bf16 hi, bf16 residual); packed pair: lo half = even k
__device__ __forceinline__ void split_pack(float va, float vb, uint32_t& p0, uint32_t& p1) {
    __nv_bfloat16 a0 = __float2bfloat16(va);
    __nv_bfloat16 b0 = __float2bfloat16(vb);
    float ra = va - __bfloat162float(a0);
    float rb = vb - __bfloat162float(b0);
    __nv_bfloat16 a1 = __float2bfloat16(ra);
    __nv_bfloat16 b1 = __float2bfloat16(rb);
    uint16_t ua0 = *reinterpret_cast<uint16_t*>(&a0);
    uint16_t ub0 = *reinterpret_cast<uint16_t*>(&b0);
    uint16_t ua1 = *reinterpret_cast<uint16_t*>(&a1);
    uint16_t ub1 = *reinterpret_cast<uint16_t*>(&b1);
    p0 = (uint32_t)ua0 | ((uint32_t)ub0 << 16);
    p1 = (uint32_t)ua1 | ((uint32_t)ub1 << 16);
}

__device__ __forceinline__ void mma_bf16(float* d, const uint32_t* a,
                                         uint32_t b0, uint32_t b1) {
    asm volatile(
        "mma.sync.aligned.m16n8k16.row.col.f32.bf16.bf16.f32 "
        "{%0,%1,%2,%3}, {%4,%5,%6,%7}, {%8,%9}, {%0,%1,%2,%3};"
        : "+f"(d[0]), "+f"(d[1]), "+f"(d[2]), "+f"(d[3])
        : "r"(a[0]), "r"(a[1]), "r"(a[2]), "r"(a[3]), "r"(b0), "r"(b1));
}

// ---------------- dtype detection ----------------
__global__ void detect_ei_kernel(const unsigned int* __restrict__ w) {
    int ok = (w[2 * threadIdx.x + 1] == 0u) ? 1 : 0;
    int all = __syncthreads_and(ok);
    if (threadIdx.x == 0) g_ei_is64 = all;
}

// ---------------- bucket fill ----------------
__global__ void __launch_bounds__(256) fill_kernel(const void* __restrict__ eiv) {
    int e = blockIdx.x * 256 + threadIdx.x;
    int s, d;
    if (g_ei_is64) {
        const long long* ei = (const long long*)eiv;
        s = (int)ei[e]; d = (int)ei[N_EDGES + e];
    } else {
        const int* ei = (const int*)eiv;
        s = ei[e]; d = ei[N_EDGES + e];
    }
    if ((unsigned)s >= N_NODES || (unsigned)d >= N_NODES) return;
    int pos = atomicAdd(&g_deg[d], 1);
    if (pos < CAP) g_bucket[d * CAP + pos] = s;
}

// ---------------- gather-aggregate layer 1 ----------------
__global__ void __launch_bounds__(256) agg1_kernel(
    const float* __restrict__ x, const float* __restrict__ eps1p,
    float* __restrict__ u1)
{
    int n = blockIdx.x * 8 + (threadIdx.x >> 5);
    int lane = threadIdx.x & 31;
    int deg = g_deg[n]; if (deg > CAP) deg = CAP;
    const int* bkt = &g_bucket[n * CAP];
    float2 acc = make_float2(0.f, 0.f);
    for (int i = 0; i < deg; i++) {
        int s = bkt[i];
        float2 v = *reinterpret_cast<const float2*>(x + (size_t)s * IN_C + lane * 2);
        acc.x += v.x; acc.y += v.y;
    }
    float ep = 1.0f + *eps1p;
    float2 xv = *reinterpret_cast<const float2*>(x + (size_t)n * IN_C + lane * 2);
    *reinterpret_cast<float2*>(u1 + (size_t)n * IN_C + lane * 2) =
        make_float2(ep * xv.x + acc.x, ep * xv.y + acc.y);
}

// ---------------- gather-aggregate layer 2 ----------------
__global__ void __launch_bounds__(256) agg2_kernel(
    const float* __restrict__ h, const float* __restrict__ eps2p,
    float* __restrict__ u2)
{
    int n = blockIdx.x * 8 + (threadIdx.x >> 5);
    int lane = threadIdx.x & 31;
    int deg = g_deg[n]; if (deg > CAP) deg = CAP;
    const int* bkt = &g_bucket[n * CAP];
    float4 acc = make_float4(0.f, 0.f, 0.f, 0.f);
    for (int i = 0; i < deg; i++) {
        int s = bkt[i];
        float4 v = *reinterpret_cast<const float4*>(h + (size_t)s * HID_C + lane * 4);
        acc.x += v.x; acc.y += v.y; acc.z += v.z; acc.w += v.w;
    }
    float ep = 1.0f + *eps2p;
    float4 hv = *reinterpret_cast<const float4*>(h + (size_t)n * HID_C + lane * 4);
    *reinterpret_cast<float4*>(u2 + (size_t)n * HID_C + lane * 4) =
        make_float4(ep * hv.x + acc.x, ep * hv.y + acc.y,
                    ep * hv.z + acc.z, ep * hv.w + acc.w);
}

// =============== shared GEMM mainloop (bf16 3-split mma) ==================
// 512 thr = 16 warps: m-stripe = wid&7 (16 rows), n-half = wid>>3 (64 cols).
// X: [128][68] u32 pairs (hi in x0, lo in x1); W: [KP][136] u32 pairs.
#define XS 68
#define WS 136
template<int KP>
__device__ __forceinline__ void mma_mainloop(
    const uint32_t* __restrict__ x0, const uint32_t* __restrict__ x1,
    const uint32_t* __restrict__ w0, const uint32_t* __restrict__ w1,
    int m0, int ntb, int r, int c, float acc[8][4])
{
    #pragma unroll
    for (int j = 0; j < 8; j++)
        #pragma unroll
        for (int i = 0; i < 4; i++) acc[j][i] = 0.0f;

    #pragma unroll
    for (int kp0 = 0; kp0 < KP; kp0 += 8) {
        uint32_t ah[4], al[4];
        ah[0] = x0[(m0 + r) * XS + kp0 + c];
        ah[1] = x0[(m0 + r + 8) * XS + kp0 + c];
        ah[2] = x0[(m0 + r) * XS + kp0 + c + 4];
        ah[3] = x0[(m0 + r + 8) * XS + kp0 + c + 4];
        al[0] = x1[(m0 + r) * XS + kp0 + c];
        al[1] = x1[(m0 + r + 8) * XS + kp0 + c];
        al[2] = x1[(m0 + r) * XS + kp0 + c + 4];
        al[3] = x1[(m0 + r + 8) * XS + kp0 + c + 4];

        const int kr0 = (kp0 + c) * WS;
        const int kr1 = (kp0 + c + 4) * WS;
        #pragma unroll
        for (int j = 0; j < 8; j++) {
            int col = (ntb + j) * 8 + r;
            uint32_t bh0 = w0[kr0 + col];
            uint32_t bh1 = w0[kr1 + col];
            uint32_t bl0 = w1[kr0 + col];
            uint32_t bl1 = w1[kr1 + col];
            mma_bf16(acc[j], ah, bh0, bh1);
            mma_bf16(acc[j], al, bh0, bh1);
            mma_bf16(acc[j], ah, bl0, bl1);
        }
    }
}

// stage weight [K][128] f32 -> packed hi/lo [K/2][136]
template<int KP>
__device__ __forceinline__ void stage_w_packed(
    const float* __restrict__ w, uint32_t* w0, uint32_t* w1, int tid)
{
    for (int i = tid; i < KP * 128; i += 512) {
        int kp = i >> 7, n = i & 127;
        float va = w[(2 * kp) * 128 + n];
        float vb = w[(2 * kp + 1) * 128 + n];
        uint32_t p0, p1;
        split_pack(va, vb, p0, p1);
        w0[kp * WS + n] = p0;
        w1[kp * WS + n] = p1;
    }
}

// ================= fused MLP layer 1: u1 -> (2 GEMMs) -> hrel ==============
// smem u32 layout:
#define M1_X0   0
#define M1_X1   (M1_X0 + 128 * XS)
#define M1_WA0  (M1_X1 + 128 * XS)          // [32][136]
#define M1_WA1  (M1_WA0 + 32 * WS)
#define M1_WB0  (M1_WA1 + 32 * WS)          // [64][136]
#define M1_WB1  (M1_WB0 + 64 * WS)
#define M1_BA   (M1_WB1 + 64 * WS)          // f32 128
#define M1_BB   (M1_BA + 128)
#define SMEM_M1 ((M1_BB + 128) * 4)

__global__ void __launch_bounds__(512, 1) mlp1_fused(
    const float* __restrict__ u1,
    const float* __restrict__ w1a, const float* __restrict__ b1a,
    const float* __restrict__ w1b, const float* __restrict__ b1b,
    float* __restrict__ hrel)
{
    extern __shared__ uint32_t smu[];
    uint32_t* x0  = smu + M1_X0;
    uint32_t* x1  = smu + M1_X1;
    uint32_t* wa0 = smu + M1_WA0;
    uint32_t* wa1 = smu + M1_WA1;
    uint32_t* wb0 = smu + M1_WB0;
    uint32_t* wb1 = smu + M1_WB1;
    float* biasA  = (float*)(smu + M1_BA);
    float* biasB  = (float*)(smu + M1_BB);

    const int tid = threadIdx.x;
    const int n0 = blockIdx.x * 128;

    stage_w_packed<32>(w1a, wa0, wa1, tid);
    stage_w_packed<64>(w1b, wb0, wb1, tid);
    if (tid < 128) { biasA[tid] = b1a[tid]; biasB[tid] = b1b[tid]; }

    // stage u1 (K=64 -> 32 pairs)
    for (int i = tid; i < 128 * 32; i += 512) {
        int n = i >> 5, kp = i & 31;
        int g = n0 + n;
        float va = 0.0f, vb = 0.0f;
        if (g < N_NODES) {
            va = u1[(size_t)g * IN_C + 2 * kp];
            vb = u1[(size_t)g * IN_C + 2 * kp + 1];
        }
        uint32_t p0, p1;
        split_pack(va, vb, p0, p1);
        x0[n * XS + kp] = p0;
        x1[n * XS + kp] = p1;
    }
    __syncthreads();

    const int lane = tid & 31;
    const int wid = tid >> 5;
    const int m0 = (wid & 7) * 16;
    const int ntb = (wid >> 3) * 8;
    const int r = lane >> 2;
    const int c = lane & 3;

    float acc[8][4];

    // ---- GEMM 1: K=64 ----
    mma_mainloop<32>(x0, x1, wa0, wa1, m0, ntb, r, c, acc);
    __syncthreads();   // all X reads done before repack

    // epilogue 1: bias+relu, split_pack straight into X (pairs 0..63)
    {
        int row0 = m0 + r, row1 = m0 + r + 8;
        #pragma unroll
        for (int j = 0; j < 8; j++) {
            int col = (ntb + j) * 8 + 2 * c;
            int p = (ntb + j) * 4 + c;
            float b0v = biasA[col], b1v = biasA[col + 1];
            float va = fmaxf(acc[j][0] + b0v, 0.0f);
            float vb = fmaxf(acc[j][1] + b1v, 0.0f);
            uint32_t p0, p1;
            split_pack(va, vb, p0, p1);
            x0[row0 * XS + p] = p0;
            x1[row0 * XS + p] = p1;
            va = fmaxf(acc[j][2] + b0v, 0.0f);
            vb = fmaxf(acc[j][3] + b1v, 0.0f);
            split_pack(va, vb, p0, p1);
            x0[row1 * XS + p] = p0;
            x1[row1 * XS + p] = p1;
        }
    }
    __syncthreads();

    // ---- GEMM 2: K=128 ----
    mma_mainloop<64>(x0, x1, wb0, wb1, m0, ntb, r, c, acc);

    // epilogue 2: bias+relu -> hrel (node-major)
    {
        int g0 = n0 + m0 + r, g1 = g0 + 8;
        #pragma unroll
        for (int j = 0; j < 8; j++) {
            int col = (ntb + j) * 8 + 2 * c;
            float b0v = biasB[col], b1v = biasB[col + 1];
            if (g0 < N_NODES) {
                float2 v = make_float2(fmaxf(acc[j][0] + b0v, 0.0f),
                                       fmaxf(acc[j][1] + b1v, 0.0f));
                *reinterpret_cast<float2*>(hrel + (size_t)g0 * HID_C + col) = v;
            }
            if (g1 < N_NODES) {
                float2 v = make_float2(fmaxf(acc[j][2] + b0v, 0.0f),
                                       fmaxf(acc[j][3] + b1v, 0.0f));
                *reinterpret_cast<float2*>(hrel + (size_t)g1 * HID_C + col) = v;
            }
        }
    }
}

// ======= fused MLP layer 2 + head: u2 -> GEMM -> 128->40 -> log_softmax ====
// smem u32 layout:
#define M2_X0   0
#define M2_X1   (M2_X0 + 128 * XS)
#define M2_WA0  (M2_X1 + 128 * XS)          // [64][136]
#define M2_WA1  (M2_WA0 + 64 * WS)
#define M2_W2B  (M2_WA1 + 64 * WS)          // f32 [40][132]
#define M2_BA   (M2_W2B + 40 * 132)
#define M2_BB   (M2_BA + 128)               // f32 64
#define M2_CORR (M2_BB + 64)                // f32 128
#define M2_OO   (M2_CORR + 128)             // f32 [128][40]
#define SMEM_M2 ((M2_OO + 128 * 40) * 4)
// tS (f32 [128][136]) overlays X0+X1 (exactly 17408 u32)

__global__ void __launch_bounds__(512, 1) mlp2_fused(
    const float* __restrict__ u2,
    const float* __restrict__ w2a, const float* __restrict__ b2a,
    const float* __restrict__ w2b, const float* __restrict__ b2b,
    float* __restrict__ out)
{
    extern __shared__ uint32_t smu[];
    uint32_t* x0  = smu + M2_X0;
    uint32_t* x1  = smu + M2_X1;
    uint32_t* wa0 = smu + M2_WA0;
    uint32_t* wa1 = smu + M2_WA1;
    float* w2bT   = (float*)(smu + M2_W2B);
    float* biasA  = (float*)(smu + M2_BA);
    float* biasB  = (float*)(smu + M2_BB);
    float* corr   = (float*)(smu + M2_CORR);
    float* oout   = (float*)(smu + M2_OO);
    float* tS     = (float*)(smu + M2_X0);   // overlay after GEMM reads done

    const int tid = threadIdx.x;
    const int n0 = blockIdx.x * 128;

    stage_w_packed<64>(w2a, wa0, wa1, tid);
    for (int i = tid; i < HID_C * OUT_C; i += 512) {
        int cc = i / OUT_C, j = i - cc * OUT_C;
        w2bT[j * 132 + cc] = w2b[i];
    }
    if (tid < 128) biasA[tid] = b2a[tid];
    if (tid < OUT_C) biasB[tid] = b2b[tid];

    for (int i = tid; i < 128 * 64; i += 512) {
        int n = i >> 6, kp = i & 63;
        int g = n0 + n;
        float va = 0.0f, vb = 0.0f;
        if (g < N_NODES) {
            va = u2[(size_t)g * HID_C + 2 * kp];
            vb = u2[(size_t)g * HID_C + 2 * kp + 1];
        }
        uint32_t p0, p1;
        split_pack(va, vb, p0, p1);
        x0[n * XS + kp] = p0;
        x1[n * XS + kp] = p1;
    }
    __syncthreads();

    const int lane = tid & 31;
    const int wid = tid >> 5;
    const int m0 = (wid & 7) * 16;
    const int ntb = (wid >> 3) * 8;
    const int r = lane >> 2;
    const int c = lane & 3;

    float acc[8][4];
    mma_mainloop<64>(x0, x1, wa0, wa1, m0, ntb, r, c, acc);
    __syncthreads();   // all X reads done before tS overlay

    // epilogue: bias+relu -> tS f32 [128][136]
    {
        int row0 = m0 + r, row1 = m0 + r + 8;
        #pragma unroll
        for (int j = 0; j < 8; j++) {
            int col = (ntb + j) * 8 + 2 * c;
            float b0v = biasA[col], b1v = biasA[col + 1];
            tS[row0 * 136 + col]     = fmaxf(acc[j][0] + b0v, 0.0f);
            tS[row0 * 136 + col + 1] = fmaxf(acc[j][1] + b1v, 0.0f);
            tS[row1 * 136 + col]     = fmaxf(acc[j][2] + b0v, 0.0f);
            tS[row1 * 136 + col + 1] = fmaxf(acc[j][3] + b1v, 0.0f);
        }
    }
    __syncthreads();

    // head: 128 -> 40
    for (int idx = tid; idx < 128 * OUT_C; idx += 512) {
        int n = idx / OUT_C;
        int j = idx - n * OUT_C;
        float a = biasB[j];
        const float* wr = &w2bT[j * 132];
        const float* tr = &tS[n * 136];
        #pragma unroll
        for (int cc = 0; cc < HID_C; cc += 4) {
            float4 wv = *reinterpret_cast<const float4*>(wr + cc);
            float4 tv = *reinterpret_cast<const float4*>(tr + cc);
            a += wv.x * tv.x + wv.y * tv.y + wv.z * tv.z + wv.w * tv.w;
        }
        oout[idx] = a;
    }
    __syncthreads();

    // log_softmax
    if (tid < 128) {
        const float* o = &oout[tid * OUT_C];
        float m = o[0];
        #pragma unroll
        for (int j = 1; j < OUT_C; j++) m = fmaxf(m, o[j]);
        float s = 0.0f;
        #pragma unroll
        for (int j = 0; j < OUT_C; j++) s += __expf(o[j] - m);
        corr[tid] = m + logf(s);
    }
    __syncthreads();

    for (int idx = tid; idx < 128 * OUT_C; idx += 512) {
        int n = idx / OUT_C;
        int g = n0 + n;
        if (g < N_NODES) out[(size_t)g * OUT_C + (idx - n * OUT_C)] = oout[idx] - corr[n];
    }
}

// ================= launch =================
extern "C" void kernel_launch(void* const* d_in, const int* in_sizes, int n_in,
                              void* d_out, int out_size)
{
    const float* x    = (const float*)d_in[0];
    const void*  ei   = d_in[1];
    const float* w1a  = (const float*)d_in[2];
    const float* b1a  = (const float*)d_in[3];
    const float* w1b  = (const float*)d_in[4];
    const float* b1b  = (const float*)d_in[5];
    const float* eps1 = (const float*)d_in[6];
    const float* w2a  = (const float*)d_in[7];
    const float* b2a  = (const float*)d_in[8];
    const float* w2b  = (const float*)d_in[9];
    const float* b2b  = (const float*)d_in[10];
    const float* eps2 = (const float*)d_in[11];
    float* out = (float*)d_out;

    float *u1, *hrel, *u2;
    int *deg;
    cudaGetSymbolAddress((void**)&u1, g_u1);
    cudaGetSymbolAddress((void**)&hrel, g_hrel);
    cudaGetSymbolAddress((void**)&u2, g_u2);
    cudaGetSymbolAddress((void**)&deg, g_deg);

    cudaFuncSetAttribute(mlp1_fused, cudaFuncAttributeMaxDynamicSharedMemorySize, SMEM_M1);
    cudaFuncSetAttribute(mlp2_fused, cudaFuncAttributeMaxDynamicSharedMemorySize, SMEM_M2);

    detect_ei_kernel<<<1, 512>>>((const unsigned int*)ei);
    cudaMemsetAsync(deg, 0, N_NODES * sizeof(int));
    fill_kernel<<<N_EDGES / 256, 256>>>(ei);

    // layer 1
    agg1_kernel<<<N_NODES / 8, 256>>>(x, eps1, u1);
    mlp1_fused<<<NB, 512, SMEM_M1>>>(u1, w1a, b1a, w1b, b1b, hrel);

    // layer 2
    agg2_kernel<<<N_NODES / 8, 256>>>(hrel, eps2, u2);
    mlp2_fused<<<NB, 512, SMEM_M2>>>(u2, w2a, b2a, w2b, b2b, out);
}

// round 14
// speedup vs baseline: 1.4998x; 1.2087x over previous
#include <cuda_runtime.h>
#include <cuda_bf16.h>
#include <cstdint>

#define N_NODES 50000
#define N_EDGES 800000
#define IN_C  64
#define HID_C 128
#define OUT_C 40
#define CAP   96
#define NB    391        // ceil(50000/128)
#define GRID_MLP 148

// ---------------- scratch ----------------
__device__ float    g_hrel[N_NODES * HID_C];
__device__ uint32_t g_u1p0[N_NODES * 32];    // packed bf16x2 hi (layer1 in, 32 k-pairs)
__device__ uint32_t g_u1p1[N_NODES * 32];    // packed bf16x2 lo
__device__ uint32_t g_u2p0[N_NODES * 64];
__device__ uint32_t g_u2p1[N_NODES * 64];
__device__ uint32_t g_wa0[32 * 128], g_wa1[32 * 128];   // w1a packed
__device__ uint32_t g_wb0[64 * 128], g_wb1[64 * 128];   // w1b packed
__device__ uint32_t g_wc0[64 * 128], g_wc1[64 * 128];   // w2a packed
__device__ int      g_deg[N_NODES];
__device__ int      g_bucket[N_NODES * CAP];
__device__ int      g_ei_is64;

// ---------------- helpers ----------------
__device__ __forceinline__ void split_pack(float va, float vb, uint32_t& p0, uint32_t& p1) {
    __nv_bfloat16 a0 = __float2bfloat16(va);
    __nv_bfloat16 b0 = __float2bfloat16(vb);
    float ra = va - __bfloat162float(a0);
    float rb = vb - __bfloat162float(b0);
    __nv_bfloat16 a1 = __float2bfloat16(ra);
    __nv_bfloat16 b1 = __float2bfloat16(rb);
    uint16_t ua0 = *reinterpret_cast<uint16_t*>(&a0);
    uint16_t ub0 = *reinterpret_cast<uint16_t*>(&b0);
    uint16_t ua1 = *reinterpret_cast<uint16_t*>(&a1);
    uint16_t ub1 = *reinterpret_cast<uint16_t*>(&b1);
    p0 = (uint32_t)ua0 | ((uint32_t)ub0 << 16);
    p1 = (uint32_t)ua1 | ((uint32_t)ub1 << 16);
}

__device__ __forceinline__ void mma_bf16(float* d, const uint32_t* a,
                                         uint32_t b0, uint32_t b1) {
    asm volatile(
        "mma.sync.aligned.m16n8k16.row.col.f32.bf16.bf16.f32 "
        "{%0,%1,%2,%3}, {%4,%5,%6,%7}, {%8,%9}, {%0,%1,%2,%3};"
        : "+f"(d[0]), "+f"(d[1]), "+f"(d[2]), "+f"(d[3])
        : "r"(a[0]), "r"(a[1]), "r"(a[2]), "r"(a[3]), "r"(b0), "r"(b1));
}

// ---------------- dtype detection ----------------
__global__ void detect_ei_kernel(const unsigned int* __restrict__ w) {
    int ok = (w[2 * threadIdx.x + 1] == 0u) ? 1 : 0;
    int all = __syncthreads_and(ok);
    if (threadIdx.x == 0) g_ei_is64 = all;
}

// ---------------- weight prep: split+pack to global ----------------
__global__ void __launch_bounds__(512) wprep_kernel(
    const float* __restrict__ w1a, const float* __restrict__ w1b,
    const float* __restrict__ w2a)
{
    int i = blockIdx.x * 512 + threadIdx.x;   // 40 blocks -> 20480
    if (i >= 20480) return;
    const float* src;
    uint32_t *d0, *d1;
    int idx;
    if (i < 4096)       { src = w1a; d0 = g_wa0; d1 = g_wa1; idx = i; }
    else if (i < 12288) { src = w1b; d0 = g_wb0; d1 = g_wb1; idx = i - 4096; }
    else                { src = w2a; d0 = g_wc0; d1 = g_wc1; idx = i - 12288; }
    int kp = idx >> 7, n = idx & 127;
    uint32_t p0, p1;
    split_pack(src[(2 * kp) * 128 + n], src[(2 * kp + 1) * 128 + n], p0, p1);
    d0[idx] = p0;
    d1[idx] = p1;
}

// ---------------- bucket fill ----------------
__global__ void __launch_bounds__(256) fill_kernel(const void* __restrict__ eiv) {
    int e = blockIdx.x * 256 + threadIdx.x;
    int s, d;
    if (g_ei_is64) {
        const long long* ei = (const long long*)eiv;
        s = (int)ei[e]; d = (int)ei[N_EDGES + e];
    } else {
        const int* ei = (const int*)eiv;
        s = ei[e]; d = ei[N_EDGES + e];
    }
    if ((unsigned)s >= N_NODES || (unsigned)d >= N_NODES) return;
    int pos = atomicAdd(&g_deg[d], 1);
    if (pos < CAP) g_bucket[d * CAP + pos] = s;
}

// ---------------- gather-aggregate layer 1 (emits packed) ----------------
__global__ void __launch_bounds__(256) agg1_kernel(
    const float* __restrict__ x, const float* __restrict__ eps1p)
{
    int n = blockIdx.x * 8 + (threadIdx.x >> 5);
    int lane = threadIdx.x & 31;
    int deg = g_deg[n]; if (deg > CAP) deg = CAP;
    const int* bkt = &g_bucket[n * CAP];
    float2 acc = make_float2(0.f, 0.f);
    for (int i = 0; i < deg; i++) {
        int s = bkt[i];
        float2 v = *reinterpret_cast<const float2*>(x + (size_t)s * IN_C + lane * 2);
        acc.x += v.x; acc.y += v.y;
    }
    float ep = 1.0f + *eps1p;
    float2 xv = *reinterpret_cast<const float2*>(x + (size_t)n * IN_C + lane * 2);
    uint32_t p0, p1;
    split_pack(ep * xv.x + acc.x, ep * xv.y + acc.y, p0, p1);
    g_u1p0[(size_t)n * 32 + lane] = p0;
    g_u1p1[(size_t)n * 32 + lane] = p1;
}

// ---------------- gather-aggregate layer 2 (emits packed) ----------------
__global__ void __launch_bounds__(256) agg2_kernel(
    const float* __restrict__ h, const float* __restrict__ eps2p)
{
    int n = blockIdx.x * 8 + (threadIdx.x >> 5);
    int lane = threadIdx.x & 31;
    int deg = g_deg[n]; if (deg > CAP) deg = CAP;
    const int* bkt = &g_bucket[n * CAP];
    float4 acc = make_float4(0.f, 0.f, 0.f, 0.f);
    for (int i = 0; i < deg; i++) {
        int s = bkt[i];
        float4 v = *reinterpret_cast<const float4*>(h + (size_t)s * HID_C + lane * 4);
        acc.x += v.x; acc.y += v.y; acc.z += v.z; acc.w += v.w;
    }
    float ep = 1.0f + *eps2p;
    float4 hv = *reinterpret_cast<const float4*>(h + (size_t)n * HID_C + lane * 4);
    uint32_t p0, p1;
    split_pack(ep * hv.x + acc.x, ep * hv.y + acc.y, p0, p1);
    g_u2p0[(size_t)n * 64 + 2 * lane] = p0;
    g_u2p1[(size_t)n * 64 + 2 * lane] = p1;
    split_pack(ep * hv.z + acc.z, ep * hv.w + acc.w, p0, p1);
    g_u2p0[(size_t)n * 64 + 2 * lane + 1] = p0;
    g_u2p1[(size_t)n * 64 + 2 * lane + 1] = p1;
}

// =============== shared GEMM mainloop (bf16 3-split mma) ==================
#define XS 68
#define WS 136
template<int KP>
__device__ __forceinline__ void mma_mainloop(
    const uint32_t* __restrict__ x0, const uint32_t* __restrict__ x1,
    const uint32_t* __restrict__ w0, const uint32_t* __restrict__ w1,
    int m0, int ntb, int r, int c, float acc[8][4])
{
    #pragma unroll
    for (int j = 0; j < 8; j++)
        #pragma unroll
        for (int i = 0; i < 4; i++) acc[j][i] = 0.0f;

    #pragma unroll
    for (int kp0 = 0; kp0 < KP; kp0 += 8) {
        uint32_t ah[4], al[4];
        ah[0] = x0[(m0 + r) * XS + kp0 + c];
        ah[1] = x0[(m0 + r + 8) * XS + kp0 + c];
        ah[2] = x0[(m0 + r) * XS + kp0 + c + 4];
        ah[3] = x0[(m0 + r + 8) * XS + kp0 + c + 4];
        al[0] = x1[(m0 + r) * XS + kp0 + c];
        al[1] = x1[(m0 + r + 8) * XS + kp0 + c];
        al[2] = x1[(m0 + r) * XS + kp0 + c + 4];
        al[3] = x1[(m0 + r + 8) * XS + kp0 + c + 4];

        const int kr0 = (kp0 + c) * WS;
        const int kr1 = (kp0 + c + 4) * WS;
        #pragma unroll
        for (int j = 0; j < 8; j++) {
            int col = (ntb + j) * 8 + r;
            uint32_t bh0 = w0[kr0 + col];
            uint32_t bh1 = w0[kr1 + col];
            uint32_t bl0 = w1[kr0 + col];
            uint32_t bl1 = w1[kr1 + col];
            mma_bf16(acc[j], ah, bh0, bh1);
            mma_bf16(acc[j], al, bh0, bh1);
            mma_bf16(acc[j], ah, bl0, bl1);
        }
    }
}

// copy pre-packed weights global -> smem (plain u32 copies)
template<int KP>
__device__ __forceinline__ void copy_w(
    const uint32_t* __restrict__ gw0, const uint32_t* __restrict__ gw1,
    uint32_t* w0, uint32_t* w1, int tid)
{
    for (int i = tid; i < KP * 128; i += 512) {
        int kp = i >> 7, n = i & 127;
        w0[kp * WS + n] = gw0[i];
        w1[kp * WS + n] = gw1[i];
    }
}

// ================= fused persistent MLP layer 1 ==============
#define M1_X0   0
#define M1_X1   (M1_X0 + 128 * XS)
#define M1_WA0  (M1_X1 + 128 * XS)          // [32][136]
#define M1_WA1  (M1_WA0 + 32 * WS)
#define M1_WB0  (M1_WA1 + 32 * WS)          // [64][136]
#define M1_WB1  (M1_WB0 + 64 * WS)
#define M1_BA   (M1_WB1 + 64 * WS)
#define M1_BB   (M1_BA + 128)
#define SMEM_M1 ((M1_BB + 128) * 4)

__global__ void __launch_bounds__(512, 1) mlp1_fused(
    const float* __restrict__ b1a, const float* __restrict__ b1b,
    float* __restrict__ hrel)
{
    extern __shared__ uint32_t smu[];
    uint32_t* x0  = smu + M1_X0;
    uint32_t* x1  = smu + M1_X1;
    uint32_t* wa0 = smu + M1_WA0;
    uint32_t* wa1 = smu + M1_WA1;
    uint32_t* wb0 = smu + M1_WB0;
    uint32_t* wb1 = smu + M1_WB1;
    float* biasA  = (float*)(smu + M1_BA);
    float* biasB  = (float*)(smu + M1_BB);

    const int tid = threadIdx.x;

    copy_w<32>(g_wa0, g_wa1, wa0, wa1, tid);
    copy_w<64>(g_wb0, g_wb1, wb0, wb1, tid);
    if (tid < 128) { biasA[tid] = b1a[tid]; biasB[tid] = b1b[tid]; }

    const int lane = tid & 31;
    const int wid = tid >> 5;
    const int m0 = (wid & 7) * 16;
    const int ntb = (wid >> 3) * 8;
    const int r = lane >> 2;
    const int c = lane & 3;

    for (int tile = blockIdx.x; tile < NB; tile += GRID_MLP) {
        const int n0 = tile * 128;
        __syncthreads();   // weights ready (1st iter); X free from prev tile

        // stage activations: plain u32 copies (zero-pad tail)
        for (int i = tid; i < 128 * 32; i += 512) {
            int n = i >> 5, kp = i & 31;
            int g = n0 + n;
            uint32_t p0 = 0u, p1 = 0u;
            if (g < N_NODES) {
                p0 = g_u1p0[(size_t)g * 32 + kp];
                p1 = g_u1p1[(size_t)g * 32 + kp];
            }
            x0[n * XS + kp] = p0;
            x1[n * XS + kp] = p1;
        }
        __syncthreads();

        float acc[8][4];
        // ---- GEMM 1: K=64 ----
        mma_mainloop<32>(x0, x1, wa0, wa1, m0, ntb, r, c, acc);
        __syncthreads();

        // epilogue 1: bias+relu, repack into X
        {
            int row0 = m0 + r, row1 = m0 + r + 8;
            #pragma unroll
            for (int j = 0; j < 8; j++) {
                int col = (ntb + j) * 8 + 2 * c;
                int p = (ntb + j) * 4 + c;
                float b0v = biasA[col], b1v = biasA[col + 1];
                uint32_t p0, p1;
                split_pack(fmaxf(acc[j][0] + b0v, 0.0f),
                           fmaxf(acc[j][1] + b1v, 0.0f), p0, p1);
                x0[row0 * XS + p] = p0;
                x1[row0 * XS + p] = p1;
                split_pack(fmaxf(acc[j][2] + b0v, 0.0f),
                           fmaxf(acc[j][3] + b1v, 0.0f), p0, p1);
                x0[row1 * XS + p] = p0;
                x1[row1 * XS + p] = p1;
            }
        }
        __syncthreads();

        // ---- GEMM 2: K=128 ----
        mma_mainloop<64>(x0, x1, wb0, wb1, m0, ntb, r, c, acc);

        // epilogue 2: bias+relu -> hrel (node-major f32)
        {
            int g0 = n0 + m0 + r, g1 = g0 + 8;
            #pragma unroll
            for (int j = 0; j < 8; j++) {
                int col = (ntb + j) * 8 + 2 * c;
                float b0v = biasB[col], b1v = biasB[col + 1];
                if (g0 < N_NODES) {
                    float2 v = make_float2(fmaxf(acc[j][0] + b0v, 0.0f),
                                           fmaxf(acc[j][1] + b1v, 0.0f));
                    *reinterpret_cast<float2*>(hrel + (size_t)g0 * HID_C + col) = v;
                }
                if (g1 < N_NODES) {
                    float2 v = make_float2(fmaxf(acc[j][2] + b0v, 0.0f),
                                           fmaxf(acc[j][3] + b1v, 0.0f));
                    *reinterpret_cast<float2*>(hrel + (size_t)g1 * HID_C + col) = v;
                }
            }
        }
    }
}

// ======= fused persistent MLP layer 2 + head ====
#define M2_X0   0
#define M2_X1   (M2_X0 + 128 * XS)
#define M2_WA0  (M2_X1 + 128 * XS)          // [64][136]
#define M2_WA1  (M2_WA0 + 64 * WS)
#define M2_W2B  (M2_WA1 + 64 * WS)          // f32 [40][132]
#define M2_BA   (M2_W2B + 40 * 132)
#define M2_BB   (M2_BA + 128)
#define M2_CORR (M2_BB + 64)
#define M2_OO   (M2_CORR + 128)
#define SMEM_M2 ((M2_OO + 128 * 40) * 4)
// tS (f32 [128][136]) overlays X0+X1

__global__ void __launch_bounds__(512, 1) mlp2_fused(
    const float* __restrict__ b2a, const float* __restrict__ w2b,
    const float* __restrict__ b2b, float* __restrict__ out)
{
    extern __shared__ uint32_t smu[];
    uint32_t* x0  = smu + M2_X0;
    uint32_t* x1  = smu + M2_X1;
    uint32_t* wa0 = smu + M2_WA0;
    uint32_t* wa1 = smu + M2_WA1;
    float* w2bT   = (float*)(smu + M2_W2B);
    float* biasA  = (float*)(smu + M2_BA);
    float* biasB  = (float*)(smu + M2_BB);
    float* corr   = (float*)(smu + M2_CORR);
    float* oout   = (float*)(smu + M2_OO);
    float* tS     = (float*)(smu + M2_X0);

    const int tid = threadIdx.x;

    copy_w<64>(g_wc0, g_wc1, wa0, wa1, tid);
    for (int i = tid; i < HID_C * OUT_C; i += 512) {
        int cc = i / OUT_C, j = i - cc * OUT_C;
        w2bT[j * 132 + cc] = w2b[i];
    }
    if (tid < 128) biasA[tid] = b2a[tid];
    if (tid < OUT_C) biasB[tid] = b2b[tid];

    const int lane = tid & 31;
    const int wid = tid >> 5;
    const int m0 = (wid & 7) * 16;
    const int ntb = (wid >> 3) * 8;
    const int r = lane >> 2;
    const int c = lane & 3;

    for (int tile = blockIdx.x; tile < NB; tile += GRID_MLP) {
        const int n0 = tile * 128;
        __syncthreads();

        for (int i = tid; i < 128 * 64; i += 512) {
            int n = i >> 6, kp = i & 63;
            int g = n0 + n;
            uint32_t p0 = 0u, p1 = 0u;
            if (g < N_NODES) {
                p0 = g_u2p0[(size_t)g * 64 + kp];
                p1 = g_u2p1[(size_t)g * 64 + kp];
            }
            x0[n * XS + kp] = p0;
            x1[n * XS + kp] = p1;
        }
        __syncthreads();

        float acc[8][4];
        mma_mainloop<64>(x0, x1, wa0, wa1, m0, ntb, r, c, acc);
        __syncthreads();   // X reads done before tS overlay

        // epilogue: bias+relu -> tS f32 [128][136]
        {
            int row0 = m0 + r, row1 = m0 + r + 8;
            #pragma unroll
            for (int j = 0; j < 8; j++) {
                int col = (ntb + j) * 8 + 2 * c;
                float b0v = biasA[col], b1v = biasA[col + 1];
                tS[row0 * 136 + col]     = fmaxf(acc[j][0] + b0v, 0.0f);
                tS[row0 * 136 + col + 1] = fmaxf(acc[j][1] + b1v, 0.0f);
                tS[row1 * 136 + col]     = fmaxf(acc[j][2] + b0v, 0.0f);
                tS[row1 * 136 + col + 1] = fmaxf(acc[j][3] + b1v, 0.0f);
            }
        }
        __syncthreads();

        // head: 128 -> 40
        for (int idx = tid; idx < 128 * OUT_C; idx += 512) {
            int n = idx / OUT_C;
            int j = idx - n * OUT_C;
            float a = biasB[j];
            const float* wr = &w2bT[j * 132];
            const float* tr = &tS[n * 136];
            #pragma unroll
            for (int cc = 0; cc < HID_C; cc += 4) {
                float4 wv = *reinterpret_cast<const float4*>(wr + cc);
                float4 tv = *reinterpret_cast<const float4*>(tr + cc);
                a += wv.x * tv.x + wv.y * tv.y + wv.z * tv.z + wv.w * tv.w;
            }
            oout[idx] = a;
        }
        __syncthreads();

        if (tid < 128) {
            const float* o = &oout[tid * OUT_C];
            float m = o[0];
            #pragma unroll
            for (int j = 1; j < OUT_C; j++) m = fmaxf(m, o[j]);
            float s = 0.0f;
            #pragma unroll
            for (int j = 0; j < OUT_C; j++) s += __expf(o[j] - m);
            corr[tid] = m + logf(s);
        }
        __syncthreads();

        for (int idx = tid; idx < 128 * OUT_C; idx += 512) {
            int n = idx / OUT_C;
            int g = n0 + n;
            if (g < N_NODES) out[(size_t)g * OUT_C + (idx - n * OUT_C)] = oout[idx] - corr[n];
        }
    }
}

// ================= launch =================
extern "C" void kernel_launch(void* const* d_in, const int* in_sizes, int n_in,
                              void* d_out, int out_size)
{
    const float* x    = (const float*)d_in[0];
    const void*  ei   = d_in[1];
    const float* w1a  = (const float*)d_in[2];
    const float* b1a  = (const float*)d_in[3];
    const float* w1b  = (const float*)d_in[4];
    const float* b1b  = (const float*)d_in[5];
    const float* eps1 = (const float*)d_in[6];
    const float* w2a  = (const float*)d_in[7];
    const float* b2a  = (const float*)d_in[8];
    const float* w2b  = (const float*)d_in[9];
    const float* b2b  = (const float*)d_in[10];
    const float* eps2 = (const float*)d_in[11];
    float* out = (float*)d_out;

    float *hrel;
    int *deg;
    cudaGetSymbolAddress((void**)&hrel, g_hrel);
    cudaGetSymbolAddress((void**)&deg, g_deg);

    cudaFuncSetAttribute(mlp1_fused, cudaFuncAttributeMaxDynamicSharedMemorySize, SMEM_M1);
    cudaFuncSetAttribute(mlp2_fused, cudaFuncAttributeMaxDynamicSharedMemorySize, SMEM_M2);

    detect_ei_kernel<<<1, 512>>>((const unsigned int*)ei);
    cudaMemsetAsync(deg, 0, N_NODES * sizeof(int));
    wprep_kernel<<<40, 512>>>(w1a, w1b, w2a);
    fill_kernel<<<N_EDGES / 256, 256>>>(ei);

    // layer 1
    agg1_kernel<<<N_NODES / 8, 256>>>(x, eps1);
    mlp1_fused<<<GRID_MLP, 512, SMEM_M1>>>(b1a, b1b, hrel);

    // layer 2
    agg2_kernel<<<N_NODES / 8, 256>>>(hrel, eps2);
    mlp2_fused<<<GRID_MLP, 512, SMEM_M2>>>(b2a, w2b, b2b, out);
}

// round 15
// speedup vs baseline: 1.5022x; 1.0016x over previous
#include <cuda_runtime.h>
#include <cuda_bf16.h>
#include <cstdint>

#define N_NODES 50000
#define N_EDGES 800000
#define IN_C  64
#define HID_C 128
#define OUT_C 40
#define CAP   96
#define NB    391        // ceil(50000/128)
#define GRID_MLP 148
#define XQ    36         // X row stride in uint4 (144 u32, 144 mod 32 == 16)

// ---------------- scratch ----------------
__device__ float    g_hrel[N_NODES * HID_C];
__device__ uint4    g_u1q[N_NODES * 16];     // layer-1 input, quad-packed (K=64)
__device__ uint4    g_u2q[N_NODES * 32];     // layer-2 input, quad-packed (K=128)
__device__ uint4    g_waq[2048];             // w1a quads (4 kblk * 512)
__device__ uint4    g_wbq[4096];             // w1b quads (8 kblk * 512)
__device__ uint4    g_wcq[4096];             // w2a quads
__device__ int      g_deg[N_NODES];
__device__ int      g_bucket[N_NODES * CAP];
__device__ int      g_ei_is64;

// ---------------- helpers ----------------
__device__ __forceinline__ void split_pack(float va, float vb, uint32_t& p0, uint32_t& p1) {
    __nv_bfloat16 a0 = __float2bfloat16(va);
    __nv_bfloat16 b0 = __float2bfloat16(vb);
    float ra = va - __bfloat162float(a0);
    float rb = vb - __bfloat162float(b0);
    __nv_bfloat16 a1 = __float2bfloat16(ra);
    __nv_bfloat16 b1 = __float2bfloat16(rb);
    uint16_t ua0 = *reinterpret_cast<uint16_t*>(&a0);
    uint16_t ub0 = *reinterpret_cast<uint16_t*>(&b0);
    uint16_t ua1 = *reinterpret_cast<uint16_t*>(&a1);
    uint16_t ub1 = *reinterpret_cast<uint16_t*>(&b1);
    p0 = (uint32_t)ua0 | ((uint32_t)ub0 << 16);
    p1 = (uint32_t)ua1 | ((uint32_t)ub1 << 16);
}

__device__ __forceinline__ void mma_bf16(float* d, const uint32_t* a,
                                         uint32_t b0, uint32_t b1) {
    asm volatile(
        "mma.sync.aligned.m16n8k16.row.col.f32.bf16.bf16.f32 "
        "{%0,%1,%2,%3}, {%4,%5,%6,%7}, {%8,%9}, {%0,%1,%2,%3};"
        : "+f"(d[0]), "+f"(d[1]), "+f"(d[2]), "+f"(d[3])
        : "r"(a[0]), "r"(a[1]), "r"(a[2]), "r"(a[3]), "r"(b0), "r"(b1));
}

// ---------------- dtype detection ----------------
__global__ void detect_ei_kernel(const unsigned int* __restrict__ w) {
    int ok = (w[2 * threadIdx.x + 1] == 0u) ? 1 : 0;
    int all = __syncthreads_and(ok);
    if (threadIdx.x == 0) g_ei_is64 = all;
}

// ---------------- weight prep: split+pack quads to global ----------------
// quad(kblk, col, c) = {hi(kp0+c), hi(kp0+c+4), lo(kp0+c), lo(kp0+c+4)}
__global__ void __launch_bounds__(512) wprep_kernel(
    const float* __restrict__ w1a, const float* __restrict__ w1b,
    const float* __restrict__ w2a)
{
    int i = blockIdx.x * 512 + threadIdx.x;   // 20 blocks -> 10240 quads
    if (i >= 10240) return;
    const float* src;
    uint4* dst;
    int q;
    if (i < 2048)      { src = w1a; dst = g_waq; q = i; }
    else if (i < 6144) { src = w1b; dst = g_wbq; q = i - 2048; }
    else               { src = w2a; dst = g_wcq; q = i - 6144; }
    int kblk = q >> 9, rem = q & 511;
    int col = rem >> 2, c = rem & 3;
    int kpA = kblk * 8 + c;
    int kpB = kpA + 4;
    uint32_t hA, lA, hB, lB;
    split_pack(src[(2 * kpA) * 128 + col], src[(2 * kpA + 1) * 128 + col], hA, lA);
    split_pack(src[(2 * kpB) * 128 + col], src[(2 * kpB + 1) * 128 + col], hB, lB);
    uint4 v; v.x = hA; v.y = hB; v.z = lA; v.w = lB;
    dst[q] = v;
}

// ---------------- bucket fill ----------------
__global__ void __launch_bounds__(256) fill_kernel(const void* __restrict__ eiv) {
    int e = blockIdx.x * 256 + threadIdx.x;
    int s, d;
    if (g_ei_is64) {
        const long long* ei = (const long long*)eiv;
        s = (int)ei[e]; d = (int)ei[N_EDGES + e];
    } else {
        const int* ei = (const int*)eiv;
        s = ei[e]; d = ei[N_EDGES + e];
    }
    if ((unsigned)s >= N_NODES || (unsigned)d >= N_NODES) return;
    int pos = atomicAdd(&g_deg[d], 1);
    if (pos < CAP) g_bucket[d * CAP + pos] = s;
}

// ---------------- gather-aggregate layer 1 (emits quad-packed) -------------
__global__ void __launch_bounds__(256) agg1_kernel(
    const float* __restrict__ x, const float* __restrict__ eps1p)
{
    int n = blockIdx.x * 8 + (threadIdx.x >> 5);
    int lane = threadIdx.x & 31;
    int deg = g_deg[n]; if (deg > CAP) deg = CAP;
    const int* bkt = &g_bucket[n * CAP];
    float2 acc = make_float2(0.f, 0.f);
    for (int i = 0; i < deg; i++) {
        int s = bkt[i];
        float2 v = *reinterpret_cast<const float2*>(x + (size_t)s * IN_C + lane * 2);
        acc.x += v.x; acc.y += v.y;
    }
    float ep = 1.0f + *eps1p;
    float2 xv = *reinterpret_cast<const float2*>(x + (size_t)n * IN_C + lane * 2);
    uint32_t p0, p1;
    split_pack(ep * xv.x + acc.x, ep * xv.y + acc.y, p0, p1);
    // kp = lane: kblk = kp>>3, c3 = kp&3, half = (kp>>2)&1
    int kblk = lane >> 3, c3 = lane & 3, half = (lane >> 2) & 1;
    uint32_t* dst = (uint32_t*)g_u1q + (size_t)n * 64 + (kblk * 4 + c3) * 4;
    dst[half] = p0;
    dst[2 + half] = p1;
}

// ---------------- gather-aggregate layer 2 (emits quad-packed) -------------
__global__ void __launch_bounds__(256) agg2_kernel(
    const float* __restrict__ h, const float* __restrict__ eps2p)
{
    int n = blockIdx.x * 8 + (threadIdx.x >> 5);
    int lane = threadIdx.x & 31;
    int deg = g_deg[n]; if (deg > CAP) deg = CAP;
    const int* bkt = &g_bucket[n * CAP];
    float4 acc = make_float4(0.f, 0.f, 0.f, 0.f);
    for (int i = 0; i < deg; i++) {
        int s = bkt[i];
        float4 v = *reinterpret_cast<const float4*>(h + (size_t)s * HID_C + lane * 4);
        acc.x += v.x; acc.y += v.y; acc.z += v.z; acc.w += v.w;
    }
    float ep = 1.0f + *eps2p;
    float4 hv = *reinterpret_cast<const float4*>(h + (size_t)n * HID_C + lane * 4);
    uint32_t* base = (uint32_t*)g_u2q + (size_t)n * 128;
    uint32_t p0, p1;
    #pragma unroll
    for (int t = 0; t < 2; t++) {
        float va = t ? (ep * hv.z + acc.z) : (ep * hv.x + acc.x);
        float vb = t ? (ep * hv.w + acc.w) : (ep * hv.y + acc.y);
        split_pack(va, vb, p0, p1);
        int kp = 2 * lane + t;
        int kblk = kp >> 3, c3 = kp & 3, half = (kp >> 2) & 1;
        uint32_t* dst = base + (kblk * 4 + c3) * 4;
        dst[half] = p0;
        dst[2 + half] = p1;
    }
}

// =============== quad-packed GEMM mainloop (bf16 3-split mma) ==============
// 512 thr = 16 warps: m-stripe = wid&7 (16 rows), n-half = wid>>3 (64 cols).
// xq: [128][XQ] uint4; wq: [KB*512] uint4.
template<int KB>
__device__ __forceinline__ void mma_mainloop(
    const uint4* __restrict__ xq, const uint4* __restrict__ wq,
    int m0, int ntb, int r, int c, float acc[8][4])
{
    #pragma unroll
    for (int j = 0; j < 8; j++)
        #pragma unroll
        for (int i = 0; i < 4; i++) acc[j][i] = 0.0f;

    #pragma unroll
    for (int kblk = 0; kblk < KB; kblk++) {
        uint4 a0 = xq[(m0 + r) * XQ + kblk * 4 + c];
        uint4 a1 = xq[(m0 + r + 8) * XQ + kblk * 4 + c];
        uint32_t ah[4] = { a0.x, a1.x, a0.y, a1.y };
        uint32_t al[4] = { a0.z, a1.z, a0.w, a1.w };
        #pragma unroll
        for (int j = 0; j < 8; j++) {
            int col = (ntb + j) * 8 + r;
            uint4 wv = wq[kblk * 512 + col * 4 + c];
            mma_bf16(acc[j], ah, wv.x, wv.y);
            mma_bf16(acc[j], al, wv.x, wv.y);
            mma_bf16(acc[j], ah, wv.z, wv.w);
        }
    }
}

// ================= fused persistent MLP layer 1 ==============
// smem u32 offsets:
#define M1_X    0                      // uint4 [128][XQ] = 18432 u32
#define M1_WA   18432                  // uint4 [2048]    = 8192 u32
#define M1_WB   26624                  // uint4 [4096]    = 16384 u32
#define M1_BA   43008
#define M1_BB   43136
#define SMEM_M1 (43264 * 4)

__global__ void __launch_bounds__(512, 1) mlp1_fused(
    const float* __restrict__ b1a, const float* __restrict__ b1b,
    float* __restrict__ hrel)
{
    extern __shared__ uint32_t smu[];
    uint4* xq = (uint4*)(smu + M1_X);
    uint4* wa = (uint4*)(smu + M1_WA);
    uint4* wb = (uint4*)(smu + M1_WB);
    float* biasA = (float*)(smu + M1_BA);
    float* biasB = (float*)(smu + M1_BB);

    const int tid = threadIdx.x;

    for (int i = tid; i < 2048; i += 512) wa[i] = g_waq[i];
    for (int i = tid; i < 4096; i += 512) wb[i] = g_wbq[i];
    if (tid < 128) { biasA[tid] = b1a[tid]; biasB[tid] = b1b[tid]; }

    const int lane = tid & 31;
    const int wid = tid >> 5;
    const int m0 = (wid & 7) * 16;
    const int ntb = (wid >> 3) * 8;
    const int r = lane >> 2;
    const int c = lane & 3;

    for (int tile = blockIdx.x; tile < NB; tile += GRID_MLP) {
        const int n0 = tile * 128;
        __syncthreads();   // weights ready (1st iter); X free from prev tile

        // stage activations: uint4 copies (16 quads/node, zero-pad tail)
        for (int i = tid; i < 128 * 16; i += 512) {
            int n = i >> 4, q = i & 15;
            int g = n0 + n;
            uint4 v = make_uint4(0u, 0u, 0u, 0u);
            if (g < N_NODES) v = g_u1q[(size_t)g * 16 + q];
            xq[n * XQ + q] = v;
        }
        __syncthreads();

        float acc[8][4];
        // ---- GEMM 1: K=64 (kblk 0..3) ----
        mma_mainloop<4>(xq, wa, m0, ntb, r, c, acc);
        __syncthreads();

        // epilogue 1: bias+relu, repack into X (pairs 0..63 -> kblk 0..7)
        {
            int row0 = m0 + r, row1 = m0 + r + 8;
            uint32_t* xu = smu + M1_X;
            #pragma unroll
            for (int j = 0; j < 8; j++) {
                int col = (ntb + j) * 8 + 2 * c;
                int p = (ntb + j) * 4 + c;
                int kblk = p >> 3, c3 = p & 3, half = (p >> 2) & 1;
                int qoff = (kblk * 4 + c3) * 4;
                float b0v = biasA[col], b1v = biasA[col + 1];
                uint32_t p0, p1;
                split_pack(fmaxf(acc[j][0] + b0v, 0.0f),
                           fmaxf(acc[j][1] + b1v, 0.0f), p0, p1);
                uint32_t* d0 = xu + row0 * 144 + qoff;
                d0[half] = p0; d0[2 + half] = p1;
                split_pack(fmaxf(acc[j][2] + b0v, 0.0f),
                           fmaxf(acc[j][3] + b1v, 0.0f), p0, p1);
                uint32_t* d1 = xu + row1 * 144 + qoff;
                d1[half] = p0; d1[2 + half] = p1;
            }
        }
        __syncthreads();

        // ---- GEMM 2: K=128 (kblk 0..7) ----
        mma_mainloop<8>(xq, wb, m0, ntb, r, c, acc);

        // epilogue 2: bias+relu -> hrel (node-major f32)
        {
            int g0 = n0 + m0 + r, g1 = g0 + 8;
            #pragma unroll
            for (int j = 0; j < 8; j++) {
                int col = (ntb + j) * 8 + 2 * c;
                float b0v = biasB[col], b1v = biasB[col + 1];
                if (g0 < N_NODES) {
                    float2 v = make_float2(fmaxf(acc[j][0] + b0v, 0.0f),
                                           fmaxf(acc[j][1] + b1v, 0.0f));
                    *reinterpret_cast<float2*>(hrel + (size_t)g0 * HID_C + col) = v;
                }
                if (g1 < N_NODES) {
                    float2 v = make_float2(fmaxf(acc[j][2] + b0v, 0.0f),
                                           fmaxf(acc[j][3] + b1v, 0.0f));
                    *reinterpret_cast<float2*>(hrel + (size_t)g1 * HID_C + col) = v;
                }
            }
        }
    }
}

// ======= fused persistent MLP layer 2 + head ====
#define M2_X    0                      // uint4 [128][XQ] = 18432 u32
#define M2_WC   18432                  // uint4 [4096]    = 16384 u32
#define M2_W2B  34816                  // f32 [40][132]   = 5280
#define M2_BA   40096
#define M2_BB   40224
#define M2_CORR 40288
#define M2_OO   40416                  // f32 [128][40]
#define SMEM_M2 (45536 * 4)
// tS (f32 [128][136] = 17408 u32) overlays X (18432)

__global__ void __launch_bounds__(512, 1) mlp2_fused(
    const float* __restrict__ b2a, const float* __restrict__ w2b,
    const float* __restrict__ b2b, float* __restrict__ out)
{
    extern __shared__ uint32_t smu[];
    uint4* xq = (uint4*)(smu + M2_X);
    uint4* wc = (uint4*)(smu + M2_WC);
    float* w2bT  = (float*)(smu + M2_W2B);
    float* biasA = (float*)(smu + M2_BA);
    float* biasB = (float*)(smu + M2_BB);
    float* corr  = (float*)(smu + M2_CORR);
    float* oout  = (float*)(smu + M2_OO);
    float* tS    = (float*)(smu + M2_X);

    const int tid = threadIdx.x;

    for (int i = tid; i < 4096; i += 512) wc[i] = g_wcq[i];
    for (int i = tid; i < HID_C * OUT_C; i += 512) {
        int cc = i / OUT_C, j = i - cc * OUT_C;
        w2bT[j * 132 + cc] = w2b[i];
    }
    if (tid < 128) biasA[tid] = b2a[tid];
    if (tid < OUT_C) biasB[tid] = b2b[tid];

    const int lane = tid & 31;
    const int wid = tid >> 5;
    const int m0 = (wid & 7) * 16;
    const int ntb = (wid >> 3) * 8;
    const int r = lane >> 2;
    const int c = lane & 3;

    for (int tile = blockIdx.x; tile < NB; tile += GRID_MLP) {
        const int n0 = tile * 128;
        __syncthreads();

        for (int i = tid; i < 128 * 32; i += 512) {
            int n = i >> 5, q = i & 31;
            int g = n0 + n;
            uint4 v = make_uint4(0u, 0u, 0u, 0u);
            if (g < N_NODES) v = g_u2q[(size_t)g * 32 + q];
            xq[n * XQ + q] = v;
        }
        __syncthreads();

        float acc[8][4];
        mma_mainloop<8>(xq, wc, m0, ntb, r, c, acc);
        __syncthreads();   // X reads done before tS overlay

        // epilogue: bias+relu -> tS f32 [128][136]
        {
            int row0 = m0 + r, row1 = m0 + r + 8;
            #pragma unroll
            for (int j = 0; j < 8; j++) {
                int col = (ntb + j) * 8 + 2 * c;
                float b0v = biasA[col], b1v = biasA[col + 1];
                tS[row0 * 136 + col]     = fmaxf(acc[j][0] + b0v, 0.0f);
                tS[row0 * 136 + col + 1] = fmaxf(acc[j][1] + b1v, 0.0f);
                tS[row1 * 136 + col]     = fmaxf(acc[j][2] + b0v, 0.0f);
                tS[row1 * 136 + col + 1] = fmaxf(acc[j][3] + b1v, 0.0f);
            }
        }
        __syncthreads();

        // head: 128 -> 40
        for (int idx = tid; idx < 128 * OUT_C; idx += 512) {
            int n = idx / OUT_C;
            int j = idx - n * OUT_C;
            float a = biasB[j];
            const float* wr = &w2bT[j * 132];
            const float* tr = &tS[n * 136];
            #pragma unroll
            for (int cc = 0; cc < HID_C; cc += 4) {
                float4 wv = *reinterpret_cast<const float4*>(wr + cc);
                float4 tv = *reinterpret_cast<const float4*>(tr + cc);
                a += wv.x * tv.x + wv.y * tv.y + wv.z * tv.z + wv.w * tv.w;
            }
            oout[idx] = a;
        }
        __syncthreads();

        if (tid < 128) {
            const float* o = &oout[tid * OUT_C];
            float m = o[0];
            #pragma unroll
            for (int j = 1; j < OUT_C; j++) m = fmaxf(m, o[j]);
            float s = 0.0f;
            #pragma unroll
            for (int j = 0; j < OUT_C; j++) s += __expf(o[j] - m);
            corr[tid] = m + logf(s);
        }
        __syncthreads();

        for (int idx = tid; idx < 128 * OUT_C; idx += 512) {
            int n = idx / OUT_C;
            int g = n0 + n;
            if (g < N_NODES) out[(size_t)g * OUT_C + (idx - n * OUT_C)] = oout[idx] - corr[n];
        }
    }
}

// ================= launch =================
extern "C" void kernel_launch(void* const* d_in, const int* in_sizes, int n_in,
                              void* d_out, int out_size)
{
    const float* x    = (const float*)d_in[0];
    const void*  ei   = d_in[1];
    const float* w1a  = (const float*)d_in[2];
    const float* b1a  = (const float*)d_in[3];
    const float* w1b  = (const float*)d_in[4];
    const float* b1b  = (const float*)d_in[5];
    const float* eps1 = (const float*)d_in[6];
    const float* w2a  = (const float*)d_in[7];
    const float* b2a  = (const float*)d_in[8];
    const float* w2b  = (const float*)d_in[9];
    const float* b2b  = (const float*)d_in[10];
    const float* eps2 = (const float*)d_in[11];
    float* out = (float*)d_out;

    float *hrel;
    int *deg;
    cudaGetSymbolAddress((void**)&hrel, g_hrel);
    cudaGetSymbolAddress((void**)&deg, g_deg);

    cudaFuncSetAttribute(mlp1_fused, cudaFuncAttributeMaxDynamicSharedMemorySize, SMEM_M1);
    cudaFuncSetAttribute(mlp2_fused, cudaFuncAttributeMaxDynamicSharedMemorySize, SMEM_M2);

    detect_ei_kernel<<<1, 512>>>((const unsigned int*)ei);
    cudaMemsetAsync(deg, 0, N_NODES * sizeof(int));
    wprep_kernel<<<20, 512>>>(w1a, w1b, w2a);
    fill_kernel<<<N_EDGES / 256, 256>>>(ei);

    // layer 1
    agg1_kernel<<<N_NODES / 8, 256>>>(x, eps1);
    mlp1_fused<<<GRID_MLP, 512, SMEM_M1>>>(b1a, b1b, hrel);

    // layer 2
    agg2_kernel<<<N_NODES / 8, 256>>>(hrel, eps2);
    mlp2_fused<<<GRID_MLP, 512, SMEM_M2>>>(b2a, w2b, b2b, out);
}

// round 16
// speedup vs baseline: 1.5366x; 1.0229x over previous
#include <cuda_runtime.h>
#include <cuda_bf16.h>
#include <cuda_fp16.h>
#include <cstdint>

#define N_NODES 50000
#define N_EDGES 800000
#define IN_C  64
#define HID_C 128
#define OUT_C 40
#define CAP   96
#define NB    391        // ceil(50000/128)
#define GRID_MLP 148
#define XQ    36         // X row stride in uint4

// ---------------- scratch ----------------
__device__ __half   g_x16[N_NODES * IN_C];   // fp16 copy of x (gather source)
__device__ __half   g_hrel[N_NODES * HID_C]; // fp16 relu(gin1 out) (gather source)
__device__ uint4    g_u1q[N_NODES * 16];     // layer-1 input, quad-packed (K=64)
__device__ uint4    g_u2q[N_NODES * 32];     // layer-2 input, quad-packed (K=128)
__device__ uint4    g_waq[2048];             // w1a quads
__device__ uint4    g_wbq[4096];             // w1b quads
__device__ uint4    g_wcq[4096];             // w2a quads
__device__ int      g_deg[N_NODES];
__device__ int      g_bucket[N_NODES * CAP];
__device__ int      g_ei_is64;

// ---------------- helpers ----------------
__device__ __forceinline__ void split_pack(float va, float vb, uint32_t& p0, uint32_t& p1) {
    __nv_bfloat16 a0 = __float2bfloat16(va);
    __nv_bfloat16 b0 = __float2bfloat16(vb);
    float ra = va - __bfloat162float(a0);
    float rb = vb - __bfloat162float(b0);
    __nv_bfloat16 a1 = __float2bfloat16(ra);
    __nv_bfloat16 b1 = __float2bfloat16(rb);
    uint16_t ua0 = *reinterpret_cast<uint16_t*>(&a0);
    uint16_t ub0 = *reinterpret_cast<uint16_t*>(&b0);
    uint16_t ua1 = *reinterpret_cast<uint16_t*>(&a1);
    uint16_t ub1 = *reinterpret_cast<uint16_t*>(&b1);
    p0 = (uint32_t)ua0 | ((uint32_t)ub0 << 16);
    p1 = (uint32_t)ua1 | ((uint32_t)ub1 << 16);
}

__device__ __forceinline__ void mma_bf16(float* d, const uint32_t* a,
                                         uint32_t b0, uint32_t b1) {
    asm volatile(
        "mma.sync.aligned.m16n8k16.row.col.f32.bf16.bf16.f32 "
        "{%0,%1,%2,%3}, {%4,%5,%6,%7}, {%8,%9}, {%0,%1,%2,%3};"
        : "+f"(d[0]), "+f"(d[1]), "+f"(d[2]), "+f"(d[3])
        : "r"(a[0]), "r"(a[1]), "r"(a[2]), "r"(a[3]), "r"(b0), "r"(b1));
}

// ---------------- dtype detection ----------------
__global__ void detect_ei_kernel(const unsigned int* __restrict__ w) {
    int ok = (w[2 * threadIdx.x + 1] == 0u) ? 1 : 0;
    int all = __syncthreads_and(ok);
    if (threadIdx.x == 0) g_ei_is64 = all;
}

// ---------------- x -> fp16 convert ----------------
__global__ void __launch_bounds__(512) xprep_kernel(const float* __restrict__ x) {
    int i = blockIdx.x * 512 + threadIdx.x;   // 1563 blocks, quads of 4
    if (i * 4 >= N_NODES * IN_C) return;
    float4 v = *reinterpret_cast<const float4*>(x + i * 4);
    __half2 h0 = __floats2half2_rn(v.x, v.y);
    __half2 h1 = __floats2half2_rn(v.z, v.w);
    *reinterpret_cast<__half2*>(g_x16 + i * 4) = h0;
    *reinterpret_cast<__half2*>(g_x16 + i * 4 + 2) = h1;
}

// ---------------- weight prep: split+pack quads ----------------
__global__ void __launch_bounds__(512) wprep_kernel(
    const float* __restrict__ w1a, const float* __restrict__ w1b,
    const float* __restrict__ w2a)
{
    int i = blockIdx.x * 512 + threadIdx.x;
    if (i >= 10240) return;
    const float* src;
    uint4* dst;
    int q;
    if (i < 2048)      { src = w1a; dst = g_waq; q = i; }
    else if (i < 6144) { src = w1b; dst = g_wbq; q = i - 2048; }
    else               { src = w2a; dst = g_wcq; q = i - 6144; }
    int kblk = q >> 9, rem = q & 511;
    int col = rem >> 2, c = rem & 3;
    int kpA = kblk * 8 + c;
    int kpB = kpA + 4;
    uint32_t hA, lA, hB, lB;
    split_pack(src[(2 * kpA) * 128 + col], src[(2 * kpA + 1) * 128 + col], hA, lA);
    split_pack(src[(2 * kpB) * 128 + col], src[(2 * kpB + 1) * 128 + col], hB, lB);
    uint4 v; v.x = hA; v.y = hB; v.z = lA; v.w = lB;
    dst[q] = v;
}

// ---------------- bucket fill ----------------
__global__ void __launch_bounds__(256) fill_kernel(const void* __restrict__ eiv) {
    int e = blockIdx.x * 256 + threadIdx.x;
    int s, d;
    if (g_ei_is64) {
        const long long* ei = (const long long*)eiv;
        s = (int)ei[e]; d = (int)ei[N_EDGES + e];
    } else {
        const int* ei = (const int*)eiv;
        s = ei[e]; d = ei[N_EDGES + e];
    }
    if ((unsigned)s >= N_NODES || (unsigned)d >= N_NODES) return;
    int pos = atomicAdd(&g_deg[d], 1);
    if (pos < CAP) g_bucket[d * CAP + pos] = s;
}

// ---------------- gather-aggregate layer 1 (fp16 gather, quad out) ---------
__global__ void __launch_bounds__(256) agg1_kernel(
    const float* __restrict__ x, const float* __restrict__ eps1p)
{
    int n = blockIdx.x * 8 + (threadIdx.x >> 5);
    int lane = threadIdx.x & 31;
    int deg = g_deg[n]; if (deg > CAP) deg = CAP;
    const int* bkt = &g_bucket[n * CAP];
    float2 acc = make_float2(0.f, 0.f);
    for (int i = 0; i < deg; i++) {
        int s = bkt[i];
        __half2 hv = *reinterpret_cast<const __half2*>(g_x16 + (size_t)s * IN_C + lane * 2);
        float2 v = __half22float2(hv);
        acc.x += v.x; acc.y += v.y;
    }
    float ep = 1.0f + *eps1p;
    float2 xv = *reinterpret_cast<const float2*>(x + (size_t)n * IN_C + lane * 2);
    uint32_t p0, p1;
    split_pack(ep * xv.x + acc.x, ep * xv.y + acc.y, p0, p1);
    int kblk = lane >> 3, c3 = lane & 3, half = (lane >> 2) & 1;
    uint32_t* dst = (uint32_t*)g_u1q + (size_t)n * 64 + (kblk * 4 + c3) * 4;
    dst[half] = p0;
    dst[2 + half] = p1;
}

// ---------------- gather-aggregate layer 2 (fp16 gather, quad out) ---------
__global__ void __launch_bounds__(256) agg2_kernel(const float* __restrict__ eps2p)
{
    int n = blockIdx.x * 8 + (threadIdx.x >> 5);
    int lane = threadIdx.x & 31;
    int deg = g_deg[n]; if (deg > CAP) deg = CAP;
    const int* bkt = &g_bucket[n * CAP];
    float4 acc = make_float4(0.f, 0.f, 0.f, 0.f);
    for (int i = 0; i < deg; i++) {
        int s = bkt[i];
        const __half2* hp = reinterpret_cast<const __half2*>(g_hrel + (size_t)s * HID_C + lane * 4);
        float2 a = __half22float2(hp[0]);
        float2 b = __half22float2(hp[1]);
        acc.x += a.x; acc.y += a.y; acc.z += b.x; acc.w += b.y;
    }
    float ep = 1.0f + *eps2p;
    const __half2* sp = reinterpret_cast<const __half2*>(g_hrel + (size_t)n * HID_C + lane * 4);
    float2 sa = __half22float2(sp[0]);
    float2 sb = __half22float2(sp[1]);
    uint32_t* base = (uint32_t*)g_u2q + (size_t)n * 128;
    uint32_t p0, p1;
    #pragma unroll
    for (int t = 0; t < 2; t++) {
        float va = t ? (ep * sb.x + acc.z) : (ep * sa.x + acc.x);
        float vb = t ? (ep * sb.y + acc.w) : (ep * sa.y + acc.y);
        split_pack(va, vb, p0, p1);
        int kp = 2 * lane + t;
        int kblk = kp >> 3, c3 = kp & 3, half = (kp >> 2) & 1;
        uint32_t* dst = base + (kblk * 4 + c3) * 4;
        dst[half] = p0;
        dst[2 + half] = p1;
    }
}

// =============== quad-packed GEMM mainloop (bf16 3-split mma) ==============
template<int KB>
__device__ __forceinline__ void mma_mainloop(
    const uint4* __restrict__ xq, const uint4* __restrict__ wq,
    int m0, int ntb, int r, int c, float acc[8][4])
{
    #pragma unroll
    for (int j = 0; j < 8; j++)
        #pragma unroll
        for (int i = 0; i < 4; i++) acc[j][i] = 0.0f;

    #pragma unroll
    for (int kblk = 0; kblk < KB; kblk++) {
        uint4 a0 = xq[(m0 + r) * XQ + kblk * 4 + c];
        uint4 a1 = xq[(m0 + r + 8) * XQ + kblk * 4 + c];
        uint32_t ah[4] = { a0.x, a1.x, a0.y, a1.y };
        uint32_t al[4] = { a0.z, a1.z, a0.w, a1.w };
        #pragma unroll
        for (int j = 0; j < 8; j++) {
            int col = (ntb + j) * 8 + r;
            uint4 wv = wq[kblk * 512 + col * 4 + c];
            mma_bf16(acc[j], ah, wv.x, wv.y);
            mma_bf16(acc[j], al, wv.x, wv.y);
            mma_bf16(acc[j], ah, wv.z, wv.w);
        }
    }
}

// ================= fused persistent MLP layer 1 ==============
#define M1_X    0
#define M1_WA   18432
#define M1_WB   26624
#define M1_BA   43008
#define M1_BB   43136
#define SMEM_M1 (43264 * 4)

__global__ void __launch_bounds__(512, 1) mlp1_fused(
    const float* __restrict__ b1a, const float* __restrict__ b1b)
{
    extern __shared__ uint32_t smu[];
    uint4* xq = (uint4*)(smu + M1_X);
    uint4* wa = (uint4*)(smu + M1_WA);
    uint4* wb = (uint4*)(smu + M1_WB);
    float* biasA = (float*)(smu + M1_BA);
    float* biasB = (float*)(smu + M1_BB);

    const int tid = threadIdx.x;

    for (int i = tid; i < 2048; i += 512) wa[i] = g_waq[i];
    for (int i = tid; i < 4096; i += 512) wb[i] = g_wbq[i];
    if (tid < 128) { biasA[tid] = b1a[tid]; biasB[tid] = b1b[tid]; }

    const int lane = tid & 31;
    const int wid = tid >> 5;
    const int m0 = (wid & 7) * 16;
    const int ntb = (wid >> 3) * 8;
    const int r = lane >> 2;
    const int c = lane & 3;

    for (int tile = blockIdx.x; tile < NB; tile += GRID_MLP) {
        const int n0 = tile * 128;
        __syncthreads();

        for (int i = tid; i < 128 * 16; i += 512) {
            int n = i >> 4, q = i & 15;
            int g = n0 + n;
            uint4 v = make_uint4(0u, 0u, 0u, 0u);
            if (g < N_NODES) v = g_u1q[(size_t)g * 16 + q];
            xq[n * XQ + q] = v;
        }
        __syncthreads();

        float acc[8][4];
        mma_mainloop<4>(xq, wa, m0, ntb, r, c, acc);
        __syncthreads();

        // epilogue 1: bias+relu, repack into X
        {
            int row0 = m0 + r, row1 = m0 + r + 8;
            uint32_t* xu = smu + M1_X;
            #pragma unroll
            for (int j = 0; j < 8; j++) {
                int col = (ntb + j) * 8 + 2 * c;
                int p = (ntb + j) * 4 + c;
                int kblk = p >> 3, c3 = p & 3, half = (p >> 2) & 1;
                int qoff = (kblk * 4 + c3) * 4;
                float b0v = biasA[col], b1v = biasA[col + 1];
                uint32_t p0, p1;
                split_pack(fmaxf(acc[j][0] + b0v, 0.0f),
                           fmaxf(acc[j][1] + b1v, 0.0f), p0, p1);
                uint32_t* d0 = xu + row0 * 144 + qoff;
                d0[half] = p0; d0[2 + half] = p1;
                split_pack(fmaxf(acc[j][2] + b0v, 0.0f),
                           fmaxf(acc[j][3] + b1v, 0.0f), p0, p1);
                uint32_t* d1 = xu + row1 * 144 + qoff;
                d1[half] = p0; d1[2 + half] = p1;
            }
        }
        __syncthreads();

        mma_mainloop<8>(xq, wb, m0, ntb, r, c, acc);

        // epilogue 2: bias+relu -> g_hrel (fp16, node-major)
        {
            int g0 = n0 + m0 + r, g1 = g0 + 8;
            #pragma unroll
            for (int j = 0; j < 8; j++) {
                int col = (ntb + j) * 8 + 2 * c;
                float b0v = biasB[col], b1v = biasB[col + 1];
                if (g0 < N_NODES) {
                    __half2 v = __floats2half2_rn(fmaxf(acc[j][0] + b0v, 0.0f),
                                                  fmaxf(acc[j][1] + b1v, 0.0f));
                    *reinterpret_cast<__half2*>(g_hrel + (size_t)g0 * HID_C + col) = v;
                }
                if (g1 < N_NODES) {
                    __half2 v = __floats2half2_rn(fmaxf(acc[j][2] + b0v, 0.0f),
                                                  fmaxf(acc[j][3] + b1v, 0.0f));
                    *reinterpret_cast<__half2*>(g_hrel + (size_t)g1 * HID_C + col) = v;
                }
            }
        }
    }
}

// ======= fused persistent MLP layer 2 + head ====
#define M2_X    0
#define M2_WC   18432
#define M2_W2B  34816
#define M2_BA   40096
#define M2_BB   40224
#define M2_CORR 40288
#define M2_OO   40416
#define SMEM_M2 (45536 * 4)

__global__ void __launch_bounds__(512, 1) mlp2_fused(
    const float* __restrict__ b2a, const float* __restrict__ w2b,
    const float* __restrict__ b2b, float* __restrict__ out)
{
    extern __shared__ uint32_t smu[];
    uint4* xq = (uint4*)(smu + M2_X);
    uint4* wc = (uint4*)(smu + M2_WC);
    float* w2bT  = (float*)(smu + M2_W2B);
    float* biasA = (float*)(smu + M2_BA);
    float* biasB = (float*)(smu + M2_BB);
    float* corr  = (float*)(smu + M2_CORR);
    float* oout  = (float*)(smu + M2_OO);
    float* tS    = (float*)(smu + M2_X);

    const int tid = threadIdx.x;

    for (int i = tid; i < 4096; i += 512) wc[i] = g_wcq[i];
    for (int i = tid; i < HID_C * OUT_C; i += 512) {
        int cc = i / OUT_C, j = i - cc * OUT_C;
        w2bT[j * 132 + cc] = w2b[i];
    }
    if (tid < 128) biasA[tid] = b2a[tid];
    if (tid < OUT_C) biasB[tid] = b2b[tid];

    const int lane = tid & 31;
    const int wid = tid >> 5;
    const int m0 = (wid & 7) * 16;
    const int ntb = (wid >> 3) * 8;
    const int r = lane >> 2;
    const int c = lane & 3;

    for (int tile = blockIdx.x; tile < NB; tile += GRID_MLP) {
        const int n0 = tile * 128;
        __syncthreads();

        for (int i = tid; i < 128 * 32; i += 512) {
            int n = i >> 5, q = i & 31;
            int g = n0 + n;
            uint4 v = make_uint4(0u, 0u, 0u, 0u);
            if (g < N_NODES) v = g_u2q[(size_t)g * 32 + q];
            xq[n * XQ + q] = v;
        }
        __syncthreads();

        float acc[8][4];
        mma_mainloop<8>(xq, wc, m0, ntb, r, c, acc);
        __syncthreads();

        {
            int row0 = m0 + r, row1 = m0 + r + 8;
            #pragma unroll
            for (int j = 0; j < 8; j++) {
                int col = (ntb + j) * 8 + 2 * c;
                float b0v = biasA[col], b1v = biasA[col + 1];
                tS[row0 * 136 + col]     = fmaxf(acc[j][0] + b0v, 0.0f);
                tS[row0 * 136 + col + 1] = fmaxf(acc[j][1] + b1v, 0.0f);
                tS[row1 * 136 + col]     = fmaxf(acc[j][2] + b0v, 0.0f);
                tS[row1 * 136 + col + 1] = fmaxf(acc[j][3] + b1v, 0.0f);
            }
        }
        __syncthreads();

        for (int idx = tid; idx < 128 * OUT_C; idx += 512) {
            int n = idx / OUT_C;
            int j = idx - n * OUT_C;
            float a = biasB[j];
            const float* wr = &w2bT[j * 132];
            const float* tr = &tS[n * 136];
            #pragma unroll
            for (int cc = 0; cc < HID_C; cc += 4) {
                float4 wv = *reinterpret_cast<const float4*>(wr + cc);
                float4 tv = *reinterpret_cast<const float4*>(tr + cc);
                a += wv.x * tv.x + wv.y * tv.y + wv.z * tv.z + wv.w * tv.w;
            }
            oout[idx] = a;
        }
        __syncthreads();

        if (tid < 128) {
            const float* o = &oout[tid * OUT_C];
            float m = o[0];
            #pragma unroll
            for (int j = 1; j < OUT_C; j++) m = fmaxf(m, o[j]);
            float s = 0.0f;
            #pragma unroll
            for (int j = 0; j < OUT_C; j++) s += __expf(o[j] - m);
            corr[tid] = m + logf(s);
        }
        __syncthreads();

        for (int idx = tid; idx < 128 * OUT_C; idx += 512) {
            int n = idx / OUT_C;
            int g = n0 + n;
            if (g < N_NODES) out[(size_t)g * OUT_C + (idx - n * OUT_C)] = oout[idx] - corr[n];
        }
    }
}

// ================= launch =================
extern "C" void kernel_launch(void* const* d_in, const int* in_sizes, int n_in,
                              void* d_out, int out_size)
{
    const float* x    = (const float*)d_in[0];
    const void*  ei   = d_in[1];
    const float* w1a  = (const float*)d_in[2];
    const float* b1a  = (const float*)d_in[3];
    const float* w1b  = (const float*)d_in[4];
    const float* b1b  = (const float*)d_in[5];
    const float* eps1 = (const float*)d_in[6];
    const float* w2a  = (const float*)d_in[7];
    const float* b2a  = (const float*)d_in[8];
    const float* w2b  = (const float*)d_in[9];
    const float* b2b  = (const float*)d_in[10];
    const float* eps2 = (const float*)d_in[11];
    float* out = (float*)d_out;

    int *deg;
    cudaGetSymbolAddress((void**)&deg, g_deg);

    cudaFuncSetAttribute(mlp1_fused, cudaFuncAttributeMaxDynamicSharedMemorySize, SMEM_M1);
    cudaFuncSetAttribute(mlp2_fused, cudaFuncAttributeMaxDynamicSharedMemorySize, SMEM_M2);

    detect_ei_kernel<<<1, 512>>>((const unsigned int*)ei);
    cudaMemsetAsync(deg, 0, N_NODES * sizeof(int));
    wprep_kernel<<<20, 512>>>(w1a, w1b, w2a);
    xprep_kernel<<<(N_NODES * IN_C / 4 + 511) / 512, 512>>>(x);
    fill_kernel<<<N_EDGES / 256, 256>>>(ei);

    // layer 1
    agg1_kernel<<<N_NODES / 8, 256>>>(x, eps1);
    mlp1_fused<<<GRID_MLP, 512, SMEM_M1>>>(b1a, b1b);

    // layer 2
    agg2_kernel<<<N_NODES / 8, 256>>>(eps2);
    mlp2_fused<<<GRID_MLP, 512, SMEM_M2>>>(b2a, w2b, b2b, out);
}

// round 17
// speedup vs baseline: 1.5629x; 1.0171x over previous
#include <cuda_runtime.h>
#include <cuda_bf16.h>
#include <cuda_fp16.h>
#include <cstdint>

#define N_NODES 50000
#define N_EDGES 800000
#define IN_C  64
#define HID_C 128
#define OUT_C 40
#define CAP   96
#define NB    391        // ceil(50000/128)
#define GRID_MLP 148
#define XQ    36         // X row stride in uint4

// ---------------- scratch ----------------
__device__ __half   g_x16[N_NODES * IN_C];   // fp16 copy of x (gather source)
__device__ __half   g_hrel[N_NODES * HID_C]; // fp16 relu(gin1 out) (gather source)
__device__ uint4    g_u1q[N_NODES * 16];     // layer-1 input, quad-packed (K=64)
__device__ uint4    g_u2q[N_NODES * 32];     // layer-2 input, quad-packed (K=128)
__device__ uint4    g_waq[2048];             // w1a quads
__device__ uint4    g_wbq[4096];             // w1b quads
__device__ uint4    g_wcq[4096];             // w2a quads
__device__ int      g_deg[N_NODES];
__device__ int      g_bucket[N_NODES * CAP];
__device__ int      g_ei_is64;

// ---------------- helpers ----------------
__device__ __forceinline__ void split_pack(float va, float vb, uint32_t& p0, uint32_t& p1) {
    __nv_bfloat16 a0 = __float2bfloat16(va);
    __nv_bfloat16 b0 = __float2bfloat16(vb);
    float ra = va - __bfloat162float(a0);
    float rb = vb - __bfloat162float(b0);
    __nv_bfloat16 a1 = __float2bfloat16(ra);
    __nv_bfloat16 b1 = __float2bfloat16(rb);
    uint16_t ua0 = *reinterpret_cast<uint16_t*>(&a0);
    uint16_t ub0 = *reinterpret_cast<uint16_t*>(&b0);
    uint16_t ua1 = *reinterpret_cast<uint16_t*>(&a1);
    uint16_t ub1 = *reinterpret_cast<uint16_t*>(&b1);
    p0 = (uint32_t)ua0 | ((uint32_t)ub0 << 16);
    p1 = (uint32_t)ua1 | ((uint32_t)ub1 << 16);
}

__device__ __forceinline__ void mma_bf16(float* d, const uint32_t* a,
                                         uint32_t b0, uint32_t b1) {
    asm volatile(
        "mma.sync.aligned.m16n8k16.row.col.f32.bf16.bf16.f32 "
        "{%0,%1,%2,%3}, {%4,%5,%6,%7}, {%8,%9}, {%0,%1,%2,%3};"
        : "+f"(d[0]), "+f"(d[1]), "+f"(d[2]), "+f"(d[3])
        : "r"(a[0]), "r"(a[1]), "r"(a[2]), "r"(a[3]), "r"(b0), "r"(b1));
}

// ---------------- fused preprocessing kernel ----------------
// blocks 0..19: wprep | 20..1582: xprep | 1583..1680: deg memset | 1681: detect
#define PREP_GRID 1682
__global__ void __launch_bounds__(512) prep_kernel(
    const float* __restrict__ w1a, const float* __restrict__ w1b,
    const float* __restrict__ w2a, const float* __restrict__ x,
    const unsigned int* __restrict__ eiw)
{
    int blk = blockIdx.x;
    int tid = threadIdx.x;

    if (blk < 20) {
        // ---- weight prep: split+pack quads ----
        int i = blk * 512 + tid;
        if (i >= 10240) return;
        const float* src;
        uint4* dst;
        int q;
        if (i < 2048)      { src = w1a; dst = g_waq; q = i; }
        else if (i < 6144) { src = w1b; dst = g_wbq; q = i - 2048; }
        else               { src = w2a; dst = g_wcq; q = i - 6144; }
        int kblk = q >> 9, rem = q & 511;
        int col = rem >> 2, c = rem & 3;
        int kpA = kblk * 8 + c;
        int kpB = kpA + 4;
        uint32_t hA, lA, hB, lB;
        split_pack(src[(2 * kpA) * 128 + col], src[(2 * kpA + 1) * 128 + col], hA, lA);
        split_pack(src[(2 * kpB) * 128 + col], src[(2 * kpB + 1) * 128 + col], hB, lB);
        uint4 v; v.x = hA; v.y = hB; v.z = lA; v.w = lB;
        dst[q] = v;
    } else if (blk < 1583) {
        // ---- x -> fp16 ----
        int i = (blk - 20) * 512 + tid;
        if (i * 4 >= N_NODES * IN_C) return;
        float4 v = *reinterpret_cast<const float4*>(x + i * 4);
        *reinterpret_cast<__half2*>(g_x16 + i * 4) = __floats2half2_rn(v.x, v.y);
        *reinterpret_cast<__half2*>(g_x16 + i * 4 + 2) = __floats2half2_rn(v.z, v.w);
    } else if (blk < 1681) {
        // ---- deg memset ----
        int i = (blk - 1583) * 512 + tid;
        if (i < N_NODES) g_deg[i] = 0;
    } else {
        // ---- dtype detect ----
        int ok = (eiw[2 * tid + 1] == 0u) ? 1 : 0;
        int all = __syncthreads_and(ok);
        if (tid == 0) g_ei_is64 = all;
    }
}

// ---------------- bucket fill: 4 edges/thread for MLP ----------------
#define FILL_GRID 391   // 391*512*4 >= 800000
__global__ void __launch_bounds__(512) fill_kernel(const void* __restrict__ eiv) {
    int base = blockIdx.x * 512 + threadIdx.x;
    const int stride = FILL_GRID * 512;
    int is64 = g_ei_is64;
    int sv[4], dv[4];
    #pragma unroll
    for (int k = 0; k < 4; k++) {
        int e = base + k * stride;
        sv[k] = -1; dv[k] = -1;
        if (e < N_EDGES) {
            if (is64) {
                const long long* ei = (const long long*)eiv;
                sv[k] = (int)ei[e]; dv[k] = (int)ei[N_EDGES + e];
            } else {
                const int* ei = (const int*)eiv;
                sv[k] = ei[e]; dv[k] = ei[N_EDGES + e];
            }
        }
    }
    #pragma unroll
    for (int k = 0; k < 4; k++) {
        if ((unsigned)sv[k] >= N_NODES || (unsigned)dv[k] >= N_NODES) continue;
        int pos = atomicAdd(&g_deg[dv[k]], 1);
        if (pos < CAP) g_bucket[dv[k] * CAP + pos] = sv[k];
    }
}

// ---------------- gather-aggregate layer 1 (fp16 gather, quad out) ---------
__global__ void __launch_bounds__(256) agg1_kernel(
    const float* __restrict__ x, const float* __restrict__ eps1p)
{
    int n = blockIdx.x * 8 + (threadIdx.x >> 5);
    int lane = threadIdx.x & 31;
    int deg = g_deg[n]; if (deg > CAP) deg = CAP;
    const int* bkt = &g_bucket[n * CAP];
    float2 acc = make_float2(0.f, 0.f);
    for (int i = 0; i < deg; i++) {
        int s = bkt[i];
        __half2 hv = *reinterpret_cast<const __half2*>(g_x16 + (size_t)s * IN_C + lane * 2);
        float2 v = __half22float2(hv);
        acc.x += v.x; acc.y += v.y;
    }
    float ep = 1.0f + *eps1p;
    float2 xv = *reinterpret_cast<const float2*>(x + (size_t)n * IN_C + lane * 2);
    uint32_t p0, p1;
    split_pack(ep * xv.x + acc.x, ep * xv.y + acc.y, p0, p1);
    int kblk = lane >> 3, c3 = lane & 3, half = (lane >> 2) & 1;
    uint32_t* dst = (uint32_t*)g_u1q + (size_t)n * 64 + (kblk * 4 + c3) * 4;
    dst[half] = p0;
    dst[2 + half] = p1;
}

// ---------------- gather-aggregate layer 2 (fp16 gather, quad out) ---------
__global__ void __launch_bounds__(256) agg2_kernel(const float* __restrict__ eps2p)
{
    int n = blockIdx.x * 8 + (threadIdx.x >> 5);
    int lane = threadIdx.x & 31;
    int deg = g_deg[n]; if (deg > CAP) deg = CAP;
    const int* bkt = &g_bucket[n * CAP];
    float4 acc = make_float4(0.f, 0.f, 0.f, 0.f);
    for (int i = 0; i < deg; i++) {
        int s = bkt[i];
        const __half2* hp = reinterpret_cast<const __half2*>(g_hrel + (size_t)s * HID_C + lane * 4);
        float2 a = __half22float2(hp[0]);
        float2 b = __half22float2(hp[1]);
        acc.x += a.x; acc.y += a.y; acc.z += b.x; acc.w += b.y;
    }
    float ep = 1.0f + *eps2p;
    const __half2* sp = reinterpret_cast<const __half2*>(g_hrel + (size_t)n * HID_C + lane * 4);
    float2 sa = __half22float2(sp[0]);
    float2 sb = __half22float2(sp[1]);
    uint32_t* base = (uint32_t*)g_u2q + (size_t)n * 128;
    uint32_t p0, p1;
    #pragma unroll
    for (int t = 0; t < 2; t++) {
        float va = t ? (ep * sb.x + acc.z) : (ep * sa.x + acc.x);
        float vb = t ? (ep * sb.y + acc.w) : (ep * sa.y + acc.y);
        split_pack(va, vb, p0, p1);
        int kp = 2 * lane + t;
        int kblk = kp >> 3, c3 = kp & 3, half = (kp >> 2) & 1;
        uint32_t* dst = base + (kblk * 4 + c3) * 4;
        dst[half] = p0;
        dst[2 + half] = p1;
    }
}

// =============== quad-packed GEMM mainloop (bf16 3-split, dual acc) ========
template<int KB>
__device__ __forceinline__ void mma_mainloop(
    const uint4* __restrict__ xq, const uint4* __restrict__ wq,
    int m0, int ntb, int r, int c, float acc[8][4])
{
    float acc2[8][4];
    #pragma unroll
    for (int j = 0; j < 8; j++)
        #pragma unroll
        for (int i = 0; i < 4; i++) { acc[j][i] = 0.0f; acc2[j][i] = 0.0f; }

    #pragma unroll
    for (int kblk = 0; kblk < KB; kblk++) {
        uint4 a0 = xq[(m0 + r) * XQ + kblk * 4 + c];
        uint4 a1 = xq[(m0 + r + 8) * XQ + kblk * 4 + c];
        uint32_t ah[4] = { a0.x, a1.x, a0.y, a1.y };
        uint32_t al[4] = { a0.z, a1.z, a0.w, a1.w };
        #pragma unroll
        for (int j = 0; j < 8; j++) {
            int col = (ntb + j) * 8 + r;
            uint4 wv = wq[kblk * 512 + col * 4 + c];
            mma_bf16(acc[j], ah, wv.x, wv.y);        // hi*hi -> chain A
            mma_bf16(acc2[j], al, wv.x, wv.y);       // lo*hi -> chain B
            if (kblk & 1) mma_bf16(acc[j], ah, wv.z, wv.w);   // hi*lo alternates
            else          mma_bf16(acc2[j], ah, wv.z, wv.w);
        }
    }
    #pragma unroll
    for (int j = 0; j < 8; j++)
        #pragma unroll
        for (int i = 0; i < 4; i++) acc[j][i] += acc2[j][i];
}

// ================= fused persistent MLP layer 1 ==============
#define M1_X    0
#define M1_WA   18432
#define M1_WB   26624
#define M1_BA   43008
#define M1_BB   43136
#define SMEM_M1 (43264 * 4)

__global__ void __launch_bounds__(512, 1) mlp1_fused(
    const float* __restrict__ b1a, const float* __restrict__ b1b)
{
    extern __shared__ uint32_t smu[];
    uint4* xq = (uint4*)(smu + M1_X);
    uint4* wa = (uint4*)(smu + M1_WA);
    uint4* wb = (uint4*)(smu + M1_WB);
    float* biasA = (float*)(smu + M1_BA);
    float* biasB = (float*)(smu + M1_BB);

    const int tid = threadIdx.x;

    for (int i = tid; i < 2048; i += 512) wa[i] = g_waq[i];
    for (int i = tid; i < 4096; i += 512) wb[i] = g_wbq[i];
    if (tid < 128) { biasA[tid] = b1a[tid]; biasB[tid] = b1b[tid]; }

    const int lane = tid & 31;
    const int wid = tid >> 5;
    const int m0 = (wid & 7) * 16;
    const int ntb = (wid >> 3) * 8;
    const int r = lane >> 2;
    const int c = lane & 3;

    for (int tile = blockIdx.x; tile < NB; tile += GRID_MLP) {
        const int n0 = tile * 128;
        __syncthreads();

        for (int i = tid; i < 128 * 16; i += 512) {
            int n = i >> 4, q = i & 15;
            int g = n0 + n;
            uint4 v = make_uint4(0u, 0u, 0u, 0u);
            if (g < N_NODES) v = g_u1q[(size_t)g * 16 + q];
            xq[n * XQ + q] = v;
        }
        __syncthreads();

        float acc[8][4];
        mma_mainloop<4>(xq, wa, m0, ntb, r, c, acc);
        __syncthreads();

        // epilogue 1: bias+relu, repack into X
        {
            int row0 = m0 + r, row1 = m0 + r + 8;
            uint32_t* xu = smu + M1_X;
            #pragma unroll
            for (int j = 0; j < 8; j++) {
                int col = (ntb + j) * 8 + 2 * c;
                int p = (ntb + j) * 4 + c;
                int kblk = p >> 3, c3 = p & 3, half = (p >> 2) & 1;
                int qoff = (kblk * 4 + c3) * 4;
                float b0v = biasA[col], b1v = biasA[col + 1];
                uint32_t p0, p1;
                split_pack(fmaxf(acc[j][0] + b0v, 0.0f),
                           fmaxf(acc[j][1] + b1v, 0.0f), p0, p1);
                uint32_t* d0 = xu + row0 * 144 + qoff;
                d0[half] = p0; d0[2 + half] = p1;
                split_pack(fmaxf(acc[j][2] + b0v, 0.0f),
                           fmaxf(acc[j][3] + b1v, 0.0f), p0, p1);
                uint32_t* d1 = xu + row1 * 144 + qoff;
                d1[half] = p0; d1[2 + half] = p1;
            }
        }
        __syncthreads();

        mma_mainloop<8>(xq, wb, m0, ntb, r, c, acc);

        // epilogue 2: bias+relu -> g_hrel (fp16, node-major)
        {
            int g0 = n0 + m0 + r, g1 = g0 + 8;
            #pragma unroll
            for (int j = 0; j < 8; j++) {
                int col = (ntb + j) * 8 + 2 * c;
                float b0v = biasB[col], b1v = biasB[col + 1];
                if (g0 < N_NODES) {
                    __half2 v = __floats2half2_rn(fmaxf(acc[j][0] + b0v, 0.0f),
                                                  fmaxf(acc[j][1] + b1v, 0.0f));
                    *reinterpret_cast<__half2*>(g_hrel + (size_t)g0 * HID_C + col) = v;
                }
                if (g1 < N_NODES) {
                    __half2 v = __floats2half2_rn(fmaxf(acc[j][2] + b0v, 0.0f),
                                                  fmaxf(acc[j][3] + b1v, 0.0f));
                    *reinterpret_cast<__half2*>(g_hrel + (size_t)g1 * HID_C + col) = v;
                }
            }
        }
    }
}

// ======= fused persistent MLP layer 2 + head ====
#define M2_X    0
#define M2_WC   18432
#define M2_W2B  34816
#define M2_BA   40096
#define M2_BB   40224
#define M2_CORR 40288
#define M2_OO   40416
#define SMEM_M2 (45536 * 4)

__global__ void __launch_bounds__(512, 1) mlp2_fused(
    const float* __restrict__ b2a, const float* __restrict__ w2b,
    const float* __restrict__ b2b, float* __restrict__ out)
{
    extern __shared__ uint32_t smu[];
    uint4* xq = (uint4*)(smu + M2_X);
    uint4* wc = (uint4*)(smu + M2_WC);
    float* w2bT  = (float*)(smu + M2_W2B);
    float* biasA = (float*)(smu + M2_BA);
    float* biasB = (float*)(smu + M2_BB);
    float* corr  = (float*)(smu + M2_CORR);
    float* oout  = (float*)(smu + M2_OO);
    float* tS    = (float*)(smu + M2_X);

    const int tid = threadIdx.x;

    for (int i = tid; i < 4096; i += 512) wc[i] = g_wcq[i];
    for (int i = tid; i < HID_C * OUT_C; i += 512) {
        int cc = i / OUT_C, j = i - cc * OUT_C;
        w2bT[j * 132 + cc] = w2b[i];
    }
    if (tid < 128) biasA[tid] = b2a[tid];
    if (tid < OUT_C) biasB[tid] = b2b[tid];

    const int lane = tid & 31;
    const int wid = tid >> 5;
    const int m0 = (wid & 7) * 16;
    const int ntb = (wid >> 3) * 8;
    const int r = lane >> 2;
    const int c = lane & 3;

    for (int tile = blockIdx.x; tile < NB; tile += GRID_MLP) {
        const int n0 = tile * 128;
        __syncthreads();

        for (int i = tid; i < 128 * 32; i += 512) {
            int n = i >> 5, q = i & 31;
            int g = n0 + n;
            uint4 v = make_uint4(0u, 0u, 0u, 0u);
            if (g < N_NODES) v = g_u2q[(size_t)g * 32 + q];
            xq[n * XQ + q] = v;
        }
        __syncthreads();

        float acc[8][4];
        mma_mainloop<8>(xq, wc, m0, ntb, r, c, acc);
        __syncthreads();

        {
            int row0 = m0 + r, row1 = m0 + r + 8;
            #pragma unroll
            for (int j = 0; j < 8; j++) {
                int col = (ntb + j) * 8 + 2 * c;
                float b0v = biasA[col], b1v = biasA[col + 1];
                tS[row0 * 136 + col]     = fmaxf(acc[j][0] + b0v, 0.0f);
                tS[row0 * 136 + col + 1] = fmaxf(acc[j][1] + b1v, 0.0f);
                tS[row1 * 136 + col]     = fmaxf(acc[j][2] + b0v, 0.0f);
                tS[row1 * 136 + col + 1] = fmaxf(acc[j][3] + b1v, 0.0f);
            }
        }
        __syncthreads();

        for (int idx = tid; idx < 128 * OUT_C; idx += 512) {
            int n = idx / OUT_C;
            int j = idx - n * OUT_C;
            float a = biasB[j];
            const float* wr = &w2bT[j * 132];
            const float* tr = &tS[n * 136];
            #pragma unroll
            for (int cc = 0; cc < HID_C; cc += 4) {
                float4 wv = *reinterpret_cast<const float4*>(wr + cc);
                float4 tv = *reinterpret_cast<const float4*>(tr + cc);
                a += wv.x * tv.x + wv.y * tv.y + wv.z * tv.z + wv.w * tv.w;
            }
            oout[idx] = a;
        }
        __syncthreads();

        if (tid < 128) {
            const float* o = &oout[tid * OUT_C];
            float m = o[0];
            #pragma unroll
            for (int j = 1; j < OUT_C; j++) m = fmaxf(m, o[j]);
            float s = 0.0f;
            #pragma unroll
            for (int j = 0; j < OUT_C; j++) s += __expf(o[j] - m);
            corr[tid] = m + logf(s);
        }
        __syncthreads();

        for (int idx = tid; idx < 128 * OUT_C; idx += 512) {
            int n = idx / OUT_C;
            int g = n0 + n;
            if (g < N_NODES) out[(size_t)g * OUT_C + (idx - n * OUT_C)] = oout[idx] - corr[n];
        }
    }
}

// ================= launch =================
extern "C" void kernel_launch(void* const* d_in, const int* in_sizes, int n_in,
                              void* d_out, int out_size)
{
    const float* x    = (const float*)d_in[0];
    const void*  ei   = d_in[1];
    const float* w1a  = (const float*)d_in[2];
    const float* b1a  = (const float*)d_in[3];
    const float* w1b  = (const float*)d_in[4];
    const float* b1b  = (const float*)d_in[5];
    const float* eps1 = (const float*)d_in[6];
    const float* w2a  = (const float*)d_in[7];
    const float* b2a  = (const float*)d_in[8];
    const float* w2b  = (const float*)d_in[9];
    const float* b2b  = (const float*)d_in[10];
    const float* eps2 = (const float*)d_in[11];
    float* out = (float*)d_out;

    cudaFuncSetAttribute(mlp1_fused, cudaFuncAttributeMaxDynamicSharedMemorySize, SMEM_M1);
    cudaFuncSetAttribute(mlp2_fused, cudaFuncAttributeMaxDynamicSharedMemorySize, SMEM_M2);

    // all preprocessing in one launch (wprep | xprep | deg memset | detect)
    prep_kernel<<<PREP_GRID, 512>>>(w1a, w1b, w2a, x, (const unsigned int*)ei);
    fill_kernel<<<FILL_GRID, 512>>>(ei);

    // layer 1
    agg1_kernel<<<N_NODES / 8, 256>>>(x, eps1);
    mlp1_fused<<<GRID_MLP, 512, SMEM_M1>>>(b1a, b1b);

    // layer 2
    agg2_kernel<<<N_NODES / 8, 256>>>(eps2);
    mlp2_fused<<<GRID_MLP, 512, SMEM_M2>>>(b2a, w2b, b2b, out);
}